// round 4
// baseline (speedup 1.0000x reference)
#include <cuda_runtime.h>
#include <cuda_bf16.h>
#include <math.h>

// Problem constants (fixed by setup_inputs)
#define B_   64
#define P_   256
#define DV   1024
#define DT   768
#define S_   512
#define NSEG 32
#define PPT  8
#define M_   (B_ * NSEG)   // 2048 GEMM rows
#define EPSV 1e-5f
#define INV_TEMP (1.0f / 0.07f)

// Scratch (device globals; no allocations allowed)
__device__ float g_A[M_ * DV];        // seg-averaged normalized features  [2048,1024]
__device__ float g_C[M_ * DT];        // seg_means = A @ W + b             [2048,768]
__device__ float g_nrm[B_ * DT];      // normalized pooled                 [64,768]
__device__ float g_sim[B_ * B_];      // similarity / TEMP                 [64,64]
__device__ int   g_rank[B_ * S_];     // placeholder rank or -1            [64,512]

// ---------------------------------------------------------------------------
// K1: per-(b,seg) block. LayerNorm each of 8 patch rows (1024), accumulate,
// write A = gamma * (sum xhat / 8) + beta.  grid=2048, 256 threads.
// ---------------------------------------------------------------------------
__global__ void k_ln_seg(const float* __restrict__ x,
                         const float* __restrict__ gamma,
                         const float* __restrict__ beta) {
    const int blk = blockIdx.x;            // b*32 + seg
    const int b = blk >> 5, seg = blk & 31;
    const int t = threadIdx.x;             // 0..255, one float4 per row
    const int wid = t >> 5, lane = t & 31;

    __shared__ float s_s[8], s_q[8];
    __shared__ float s_mean, s_inv;

    float4 acc = make_float4(0.f, 0.f, 0.f, 0.f);

    for (int pp = 0; pp < PPT; ++pp) {
        const int p = seg * PPT + pp;
        const float4* row = (const float4*)(x + ((size_t)(b * P_ + p)) * DV);
        float4 v = row[t];
        float s  = v.x + v.y + v.z + v.w;
        float sq = v.x * v.x + v.y * v.y + v.z * v.z + v.w * v.w;
        #pragma unroll
        for (int off = 16; off > 0; off >>= 1) {
            s  += __shfl_down_sync(0xffffffffu, s,  off);
            sq += __shfl_down_sync(0xffffffffu, sq, off);
        }
        if (lane == 0) { s_s[wid] = s; s_q[wid] = sq; }
        __syncthreads();
        if (t == 0) {
            float ts = 0.f, tq = 0.f;
            #pragma unroll
            for (int w = 0; w < 8; ++w) { ts += s_s[w]; tq += s_q[w]; }
            float mean = ts * (1.0f / DV);
            float var  = tq * (1.0f / DV) - mean * mean;
            s_mean = mean;
            s_inv  = rsqrtf(var + EPSV);
        }
        __syncthreads();
        const float mean = s_mean, inv = s_inv;
        acc.x += (v.x - mean) * inv;
        acc.y += (v.y - mean) * inv;
        acc.z += (v.z - mean) * inv;
        acc.w += (v.w - mean) * inv;
    }

    const float4 g  = ((const float4*)gamma)[t];
    const float4 bb = ((const float4*)beta)[t];
    float4 o;
    o.x = g.x * acc.x * 0.125f + bb.x;
    o.y = g.y * acc.y * 0.125f + bb.y;
    o.z = g.z * acc.z * 0.125f + bb.z;
    o.w = g.w * acc.w * 0.125f + bb.w;
    ((float4*)(g_A + (size_t)blk * DV))[t] = o;
}

// ---------------------------------------------------------------------------
// K2: GEMM  C[2048,768] = A[2048,1024] @ W[1024,768] + bias.
// Tiles: BM=128, BN=64, BK=16, 256 threads, 8x4 per thread.
// grid = (768/64, 2048/128) = (12,16)
// ---------------------------------------------------------------------------
#define BM 128
#define BN 64
#define BK 16
__global__ void k_gemm(const float* __restrict__ W,
                       const float* __restrict__ bias) {
    __shared__ float As[BK][BM];
    __shared__ float Bs[BK][BN];

    const int bm = blockIdx.y * BM;
    const int bn = blockIdx.x * BN;
    const int tid = threadIdx.x;          // 256
    const int tx = tid & 15;              // 0..15 -> 4 cols each
    const int ty = tid >> 4;              // 0..15 -> 8 rows each

    float acc[8][4];
    #pragma unroll
    for (int i = 0; i < 8; ++i)
        #pragma unroll
        for (int j = 0; j < 4; ++j) acc[i][j] = 0.f;

    for (int k0 = 0; k0 < DV; k0 += BK) {
        // A tile: 128 rows x 16 k  = 512 float4 (transposed into As[k][m])
        #pragma unroll
        for (int l = 0; l < 2; ++l) {
            int idx = tid + l * 256;      // float4 index 0..511
            int r = idx >> 2;             // row within tile
            int c4 = idx & 3;             // which group of 4 k's
            float4 v = *(const float4*)(g_A + (size_t)(bm + r) * DV + k0 + c4 * 4);
            As[c4 * 4 + 0][r] = v.x;
            As[c4 * 4 + 1][r] = v.y;
            As[c4 * 4 + 2][r] = v.z;
            As[c4 * 4 + 3][r] = v.w;
        }
        // B tile: 16 k x 64 n = 256 float4
        {
            int r = tid >> 4;             // k row 0..15
            int c = tid & 15;             // float4 col 0..15
            float4 v = *(const float4*)(W + (size_t)(k0 + r) * DT + bn + c * 4);
            *(float4*)&Bs[r][c * 4] = v;
        }
        __syncthreads();

        #pragma unroll
        for (int k = 0; k < BK; ++k) {
            float4 a0 = *(const float4*)&As[k][ty * 8];
            float4 a1 = *(const float4*)&As[k][ty * 8 + 4];
            float4 bv = *(const float4*)&Bs[k][tx * 4];
            float a[8] = {a0.x, a0.y, a0.z, a0.w, a1.x, a1.y, a1.z, a1.w};
            float bb[4] = {bv.x, bv.y, bv.z, bv.w};
            #pragma unroll
            for (int i = 0; i < 8; ++i)
                #pragma unroll
                for (int j = 0; j < 4; ++j)
                    acc[i][j] = fmaf(a[i], bb[j], acc[i][j]);
        }
        __syncthreads();
    }

    const float4 bsv = *(const float4*)(bias + bn + tx * 4);
    #pragma unroll
    for (int i = 0; i < 8; ++i) {
        float4 o;
        o.x = acc[i][0] + bsv.x;
        o.y = acc[i][1] + bsv.y;
        o.z = acc[i][2] + bsv.z;
        o.w = acc[i][3] + bsv.w;
        *(float4*)(g_C + (size_t)(bm + ty * 8 + i) * DT + bn + tx * 4) = o;
    }
}

// ---------------------------------------------------------------------------
// K3: pooled[b] = mean over 32 segs of seg_means; normalize -> g_nrm.
// grid=64, 256 threads (3 elems each).
// ---------------------------------------------------------------------------
__global__ void k_pool(void) {
    const int b = blockIdx.x;
    const int t = threadIdx.x;
    const int wid = t >> 5, lane = t & 31;
    __shared__ float s_q[8];
    __shared__ float s_inv;

    float v[3];
    #pragma unroll
    for (int i = 0; i < 3; ++i) {
        int d = t + i * 256;
        float s = 0.f;
        #pragma unroll 4
        for (int seg = 0; seg < NSEG; ++seg)
            s += g_C[(size_t)(b * NSEG + seg) * DT + d];
        v[i] = s * (1.0f / NSEG);
    }
    float sq = v[0] * v[0] + v[1] * v[1] + v[2] * v[2];
    #pragma unroll
    for (int off = 16; off > 0; off >>= 1)
        sq += __shfl_down_sync(0xffffffffu, sq, off);
    if (lane == 0) s_q[wid] = sq;
    __syncthreads();
    if (t == 0) {
        float tq = 0.f;
        #pragma unroll
        for (int w = 0; w < 8; ++w) tq += s_q[w];
        s_inv = rsqrtf(tq);
    }
    __syncthreads();
    const float inv = s_inv;
    #pragma unroll
    for (int i = 0; i < 3; ++i)
        g_nrm[(size_t)b * DT + t + i * 256] = v[i] * inv;
}

// ---------------------------------------------------------------------------
// K4a: sim[i][j] = (nrm_i . nrm_j) / TEMP. grid=64, 256 threads (8 warps x 8 j).
// ---------------------------------------------------------------------------
__global__ void k_sim(void) {
    const int i = blockIdx.x;
    const int wid = threadIdx.x >> 5, lane = threadIdx.x & 31;
    const float* ri = g_nrm + (size_t)i * DT;
    #pragma unroll
    for (int jj = 0; jj < 8; ++jj) {
        int j = wid * 8 + jj;
        const float* rj = g_nrm + (size_t)j * DT;
        float s = 0.f;
        #pragma unroll 6
        for (int d = lane; d < DT; d += 32)
            s = fmaf(ri[d], rj[d], s);
        #pragma unroll
        for (int off = 16; off > 0; off >>= 1)
            s += __shfl_down_sync(0xffffffffu, s, off);
        if (lane == 0) g_sim[i * B_ + j] = s * INV_TEMP;
    }
}

// ---------------------------------------------------------------------------
// K4b: loss (sim symmetric => ce_row == ce_col => loss = row CE).
// 1 block, 64 threads.
// ---------------------------------------------------------------------------
__global__ void k_loss(float* __restrict__ loss_out) {
    const int i = threadIdx.x;  // 0..63
    __shared__ float s_l[64];
    float m = -1e30f;
    #pragma unroll 8
    for (int j = 0; j < B_; ++j) m = fmaxf(m, g_sim[i * B_ + j]);
    float s = 0.f;
    #pragma unroll 8
    for (int j = 0; j < B_; ++j) s += expf(g_sim[i * B_ + j] - m);
    float lse = m + logf(s);
    s_l[i] = lse - g_sim[i * B_ + i];
    __syncthreads();
    if (i == 0) {
        float tot = 0.f;
        #pragma unroll
        for (int j = 0; j < B_; ++j) tot += s_l[j];
        *loss_out = tot * (1.0f / B_);
    }
}

// ---------------------------------------------------------------------------
// K5a: per-row inclusive scan of placeholder mask -> rank (or -1).
// grid=64, 512 threads.
// ---------------------------------------------------------------------------
__global__ void k_rank(const int* __restrict__ ids,
                       const int* __restrict__ ph_ptr) {
    const int b = blockIdx.x, s = threadIdx.x;
    const int ph = *ph_ptr;
    __shared__ int sc[S_];
    const int m = (ids[b * S_ + s] == ph) ? 1 : 0;
    sc[s] = m;
    __syncthreads();
    for (int off = 1; off < S_; off <<= 1) {
        int v = (s >= off) ? sc[s - off] : 0;
        __syncthreads();
        sc[s] += v;
        __syncthreads();
    }
    const int rank = sc[s] - 1;
    g_rank[b * S_ + s] = (m && rank < NSEG) ? rank : -1;
}

// ---------------------------------------------------------------------------
// K5b: text_emb: copy either seg_means[b,rank] or wte[id].  grid=B*S, 192 thr.
// ---------------------------------------------------------------------------
__global__ void k_emb(const float* __restrict__ wte,
                      const int* __restrict__ ids,
                      float* __restrict__ out) {
    const int blk = blockIdx.x;   // b*512 + s
    const int t = threadIdx.x;    // 0..191 (float4)
    const int r = g_rank[blk];
    const float* src;
    if (r >= 0) {
        int b = blk >> 9;
        src = g_C + (size_t)(b * NSEG + r) * DT;
    } else {
        int id = ids[blk];
        src = wte + (size_t)id * DT;
    }
    ((float4*)(out + (size_t)blk * DT))[t] = ((const float4*)src)[t];
}

// ---------------------------------------------------------------------------
extern "C" void kernel_launch(void* const* d_in, const int* in_sizes, int n_in,
                              void* d_out, int out_size) {
    const float* vis   = (const float*)d_in[0];  // [64,256,1024]
    const float* gamma = (const float*)d_in[1];  // [1024]
    const float* beta  = (const float*)d_in[2];  // [1024]
    const float* Wp    = (const float*)d_in[3];  // [1024,768]
    const float* bp    = (const float*)d_in[4];  // [768]
    const float* wte   = (const float*)d_in[5];  // [50257,768]
    const int*   ids   = (const int*)d_in[6];    // [64,512]
    const int*   ph    = (const int*)d_in[7];    // scalar

    float* out = (float*)d_out;
    // layout: text_emb [B*S*Dt] then loss scalar (last element)
    float* loss_out = out + (out_size - 1);

    k_ln_seg<<<M_, 256>>>(vis, gamma, beta);
    {
        dim3 grid(DT / BN, M_ / BM);
        k_gemm<<<grid, 256>>>(Wp, bp);
    }
    k_pool<<<B_, 256>>>();
    k_sim<<<B_, 256>>>();
    k_loss<<<1, 64>>>(loss_out);
    k_rank<<<B_, S_>>>(ids, ph);
    k_emb<<<B_ * S_, DT / 4>>>(wte, ids, out);
}

// round 5
// speedup vs baseline: 1.1213x; 1.1213x over previous
#include <cuda_runtime.h>
#include <cuda_bf16.h>
#include <math.h>

// Problem constants (fixed by setup_inputs)
#define B_   64
#define P_   256
#define DV   1024
#define DT   768
#define S_   512
#define NSEG 32
#define PPT  8
#define M_   (B_ * NSEG)   // 2048 GEMM rows
#define EPSV 1e-5f
#define INV_TEMP (1.0f / 0.07f)

// Scratch (device globals; no allocations allowed)
__device__ float g_A[M_ * DV];        // seg-averaged normalized features  [2048,1024]
__device__ float g_C[M_ * DT];        // seg_means = A @ W + b             [2048,768]
__device__ float g_nrm[B_ * DT];      // normalized pooled                 [64,768]
__device__ float g_sim[B_ * B_];      // similarity / TEMP                 [64,64]
__device__ int   g_rank[B_ * S_];     // placeholder rank or -1            [64,512]

// ---- packed f32x2 helpers (Blackwell FFMA2 path) --------------------------
__device__ __forceinline__ unsigned long long pack2(float x, float y) {
    unsigned long long r;
    asm("mov.b64 %0, {%1, %2};" : "=l"(r) : "f"(x), "f"(y));
    return r;
}
__device__ __forceinline__ void unpack2(unsigned long long v, float& x, float& y) {
    asm("mov.b64 {%0, %1}, %2;" : "=f"(x), "=f"(y) : "l"(v));
}
__device__ __forceinline__ unsigned long long fma2(unsigned long long a,
                                                   unsigned long long b,
                                                   unsigned long long c) {
    unsigned long long d;
    asm("fma.rn.f32x2 %0, %1, %2, %3;" : "=l"(d) : "l"(a), "l"(b), "l"(c));
    return d;
}

// ---------------------------------------------------------------------------
// K1: per-(b,seg) block. Preload all 8 patch rows (MLP=8), LayerNorm each,
// accumulate; write A = gamma * (sum xhat / 8) + beta.  grid=2048, 256 thr.
// Only 2 block barriers total.
// ---------------------------------------------------------------------------
__global__ void k_ln_seg(const float* __restrict__ x,
                         const float* __restrict__ gamma,
                         const float* __restrict__ beta) {
    const int blk = blockIdx.x;            // b*32 + seg
    const int b = blk >> 5, seg = blk & 31;
    const int t = threadIdx.x;             // 0..255, one float4 per row
    const int wid = t >> 5, lane = t & 31;

    __shared__ float s_s[8][8], s_q[8][8];
    __shared__ float2 s_mi[8];

    const float* base = x + ((size_t)(b * P_ + seg * PPT)) * DV;

    float4 v[8];
    #pragma unroll
    for (int pp = 0; pp < PPT; ++pp)
        v[pp] = ((const float4*)(base + (size_t)pp * DV))[t];

    #pragma unroll
    for (int pp = 0; pp < PPT; ++pp) {
        float s  = v[pp].x + v[pp].y + v[pp].z + v[pp].w;
        float sq = v[pp].x * v[pp].x + v[pp].y * v[pp].y
                 + v[pp].z * v[pp].z + v[pp].w * v[pp].w;
        #pragma unroll
        for (int off = 16; off > 0; off >>= 1) {
            s  += __shfl_down_sync(0xffffffffu, s,  off);
            sq += __shfl_down_sync(0xffffffffu, sq, off);
        }
        if (lane == 0) { s_s[pp][wid] = s; s_q[pp][wid] = sq; }
    }
    __syncthreads();

    // warp `wid` reduces the 8 partials for patch row `wid`
    if (lane < 8) {
        float s = s_s[wid][lane];
        float q = s_q[wid][lane];
        #pragma unroll
        for (int off = 4; off > 0; off >>= 1) {
            s += __shfl_down_sync(0x000000ffu, s, off);
            q += __shfl_down_sync(0x000000ffu, q, off);
        }
        if (lane == 0) {
            float mean = s * (1.0f / DV);
            float var  = q * (1.0f / DV) - mean * mean;
            s_mi[wid] = make_float2(mean, rsqrtf(var + EPSV));
        }
    }
    __syncthreads();

    float4 acc = make_float4(0.f, 0.f, 0.f, 0.f);
    #pragma unroll
    for (int pp = 0; pp < PPT; ++pp) {
        const float2 mi = s_mi[pp];
        acc.x += (v[pp].x - mi.x) * mi.y;
        acc.y += (v[pp].y - mi.x) * mi.y;
        acc.z += (v[pp].z - mi.x) * mi.y;
        acc.w += (v[pp].w - mi.x) * mi.y;
    }

    const float4 g  = ((const float4*)gamma)[t];
    const float4 bb = ((const float4*)beta)[t];
    float4 o;
    o.x = g.x * acc.x * 0.125f + bb.x;
    o.y = g.y * acc.y * 0.125f + bb.y;
    o.z = g.z * acc.z * 0.125f + bb.z;
    o.w = g.w * acc.w * 0.125f + bb.w;
    ((float4*)(g_A + (size_t)blk * DV))[t] = o;
}

// ---------------------------------------------------------------------------
// K2: GEMM  C[2048,768] = A[2048,1024] @ W[1024,768] + bias.
// BM=128, BN=64, BK=16, 256 threads, 8x4 per thread, accumulators packed
// along M as f32x2 pairs (FFMA2). Double-buffered smem (1 sync / k-tile).
// grid = (768/64, 2048/128) = (12,16) = 192 blocks.
// ---------------------------------------------------------------------------
#define BM 128
#define BN 64
#define BK 16
__global__ void k_gemm(const float* __restrict__ W,
                       const float* __restrict__ bias) {
    __shared__ __align__(16) float As[2][BK][BM];
    __shared__ __align__(16) float Bs[2][BK][BN];

    const int bm = blockIdx.y * BM;
    const int bn = blockIdx.x * BN;
    const int tid = threadIdx.x;          // 256
    const int tx = tid & 15;              // 0..15 -> 4 cols each
    const int ty = tid >> 4;              // 0..15 -> 8 rows each (4 pairs)

    // A staging: idx = tid + l*256 -> float4 index 0..511
    const int ar0 = (tid) >> 2,        ac0 = (tid) & 3;
    const int ar1 = (tid + 256) >> 2,  ac1 = (tid + 256) & 3;
    // B staging
    const int brow = tid >> 4, bcol = tid & 15;

    unsigned long long acc[4][4];         // [row-pair][col], 32 floats
    #pragma unroll
    for (int i = 0; i < 4; ++i)
        #pragma unroll
        for (int j = 0; j < 4; ++j) acc[i][j] = 0ull;

    float4 va0, va1, vb;
    // prefetch tile 0
    va0 = *(const float4*)(g_A + (size_t)(bm + ar0) * DV + ac0 * 4);
    va1 = *(const float4*)(g_A + (size_t)(bm + ar1) * DV + ac1 * 4);
    vb  = *(const float4*)(W + (size_t)brow * DT + bn + bcol * 4);
    {
        As[0][ac0 * 4 + 0][ar0] = va0.x; As[0][ac0 * 4 + 1][ar0] = va0.y;
        As[0][ac0 * 4 + 2][ar0] = va0.z; As[0][ac0 * 4 + 3][ar0] = va0.w;
        As[0][ac1 * 4 + 0][ar1] = va1.x; As[0][ac1 * 4 + 1][ar1] = va1.y;
        As[0][ac1 * 4 + 2][ar1] = va1.z; As[0][ac1 * 4 + 3][ar1] = va1.w;
        *(float4*)&Bs[0][brow][bcol * 4] = vb;
    }
    __syncthreads();

    const int NT = DV / BK;  // 64
    int cur = 0;
    for (int t = 0; t < NT; ++t) {
        const int k0n = (t + 1) * BK;
        if (t + 1 < NT) {
            va0 = *(const float4*)(g_A + (size_t)(bm + ar0) * DV + k0n + ac0 * 4);
            va1 = *(const float4*)(g_A + (size_t)(bm + ar1) * DV + k0n + ac1 * 4);
            vb  = *(const float4*)(W + (size_t)(k0n + brow) * DT + bn + bcol * 4);
        }

        #pragma unroll
        for (int k = 0; k < BK; ++k) {
            unsigned long long a0 = *(const unsigned long long*)&As[cur][k][ty * 8 + 0];
            unsigned long long a1 = *(const unsigned long long*)&As[cur][k][ty * 8 + 2];
            unsigned long long a2 = *(const unsigned long long*)&As[cur][k][ty * 8 + 4];
            unsigned long long a3 = *(const unsigned long long*)&As[cur][k][ty * 8 + 6];
            float4 bv = *(const float4*)&Bs[cur][k][tx * 4];
            unsigned long long b0 = pack2(bv.x, bv.x);
            unsigned long long b1 = pack2(bv.y, bv.y);
            unsigned long long b2 = pack2(bv.z, bv.z);
            unsigned long long b3 = pack2(bv.w, bv.w);
            acc[0][0] = fma2(a0, b0, acc[0][0]);
            acc[0][1] = fma2(a0, b1, acc[0][1]);
            acc[0][2] = fma2(a0, b2, acc[0][2]);
            acc[0][3] = fma2(a0, b3, acc[0][3]);
            acc[1][0] = fma2(a1, b0, acc[1][0]);
            acc[1][1] = fma2(a1, b1, acc[1][1]);
            acc[1][2] = fma2(a1, b2, acc[1][2]);
            acc[1][3] = fma2(a1, b3, acc[1][3]);
            acc[2][0] = fma2(a2, b0, acc[2][0]);
            acc[2][1] = fma2(a2, b1, acc[2][1]);
            acc[2][2] = fma2(a2, b2, acc[2][2]);
            acc[2][3] = fma2(a2, b3, acc[2][3]);
            acc[3][0] = fma2(a3, b0, acc[3][0]);
            acc[3][1] = fma2(a3, b1, acc[3][1]);
            acc[3][2] = fma2(a3, b2, acc[3][2]);
            acc[3][3] = fma2(a3, b3, acc[3][3]);
        }

        if (t + 1 < NT) {
            const int nxt = cur ^ 1;
            As[nxt][ac0 * 4 + 0][ar0] = va0.x; As[nxt][ac0 * 4 + 1][ar0] = va0.y;
            As[nxt][ac0 * 4 + 2][ar0] = va0.z; As[nxt][ac0 * 4 + 3][ar0] = va0.w;
            As[nxt][ac1 * 4 + 0][ar1] = va1.x; As[nxt][ac1 * 4 + 1][ar1] = va1.y;
            As[nxt][ac1 * 4 + 2][ar1] = va1.z; As[nxt][ac1 * 4 + 3][ar1] = va1.w;
            *(float4*)&Bs[nxt][brow][bcol * 4] = vb;
        }
        __syncthreads();
        cur ^= 1;
    }

    const float4 bsv = *(const float4*)(bias + bn + tx * 4);
    #pragma unroll
    for (int ii = 0; ii < 4; ++ii) {
        float lo0, hi0, lo1, hi1, lo2, hi2, lo3, hi3;
        unpack2(acc[ii][0], lo0, hi0);
        unpack2(acc[ii][1], lo1, hi1);
        unpack2(acc[ii][2], lo2, hi2);
        unpack2(acc[ii][3], lo3, hi3);
        const int m0 = bm + ty * 8 + 2 * ii;
        float4 o0, o1;
        o0.x = lo0 + bsv.x; o0.y = lo1 + bsv.y; o0.z = lo2 + bsv.z; o0.w = lo3 + bsv.w;
        o1.x = hi0 + bsv.x; o1.y = hi1 + bsv.y; o1.z = hi2 + bsv.z; o1.w = hi3 + bsv.w;
        *(float4*)(g_C + (size_t)m0 * DT + bn + tx * 4) = o0;
        *(float4*)(g_C + (size_t)(m0 + 1) * DT + bn + tx * 4) = o1;
    }
}

// ---------------------------------------------------------------------------
// K3: pooled[b] = mean over 32 segs of seg_means; normalize -> g_nrm.
// grid=64, 192 threads (1 float4 each).
// ---------------------------------------------------------------------------
__global__ void k_pool(void) {
    const int b = blockIdx.x;
    const int t = threadIdx.x;            // 0..191
    const int wid = t >> 5, lane = t & 31;
    __shared__ float s_q[6];
    __shared__ float s_inv;

    float4 s = make_float4(0.f, 0.f, 0.f, 0.f);
    #pragma unroll 4
    for (int seg = 0; seg < NSEG; ++seg) {
        float4 v = ((const float4*)(g_C + (size_t)(b * NSEG + seg) * DT))[t];
        s.x += v.x; s.y += v.y; s.z += v.z; s.w += v.w;
    }
    s.x *= (1.0f / NSEG); s.y *= (1.0f / NSEG);
    s.z *= (1.0f / NSEG); s.w *= (1.0f / NSEG);

    float sq = s.x * s.x + s.y * s.y + s.z * s.z + s.w * s.w;
    #pragma unroll
    for (int off = 16; off > 0; off >>= 1)
        sq += __shfl_down_sync(0xffffffffu, sq, off);
    if (lane == 0) s_q[wid] = sq;
    __syncthreads();
    if (t == 0) {
        float tq = 0.f;
        #pragma unroll
        for (int w = 0; w < 6; ++w) tq += s_q[w];
        s_inv = rsqrtf(tq);
    }
    __syncthreads();
    const float inv = s_inv;
    float4 o;
    o.x = s.x * inv; o.y = s.y * inv; o.z = s.z * inv; o.w = s.w * inv;
    ((float4*)(g_nrm + (size_t)b * DT))[t] = o;
}

// ---------------------------------------------------------------------------
// K4a: sim[i][j] = (nrm_i . nrm_j) / TEMP. grid=(64,4), 256 threads.
// Each warp handles 2 j's; ri cached in registers as float4.
// ---------------------------------------------------------------------------
__global__ void k_sim(void) {
    const int i = blockIdx.x;
    const int wid = threadIdx.x >> 5, lane = threadIdx.x & 31;
    const float4* Ri = (const float4*)(g_nrm + (size_t)i * DT);
    float4 ri[6];
    #pragma unroll
    for (int c = 0; c < 6; ++c) ri[c] = Ri[lane + 32 * c];

    #pragma unroll
    for (int jj = 0; jj < 2; ++jj) {
        const int j = blockIdx.y * 16 + wid * 2 + jj;
        const float4* Rj = (const float4*)(g_nrm + (size_t)j * DT);
        float s = 0.f;
        #pragma unroll
        for (int c = 0; c < 6; ++c) {
            float4 r = Rj[lane + 32 * c];
            s = fmaf(ri[c].x, r.x, s);
            s = fmaf(ri[c].y, r.y, s);
            s = fmaf(ri[c].z, r.z, s);
            s = fmaf(ri[c].w, r.w, s);
        }
        #pragma unroll
        for (int off = 16; off > 0; off >>= 1)
            s += __shfl_down_sync(0xffffffffu, s, off);
        if (lane == 0) g_sim[i * B_ + j] = s * INV_TEMP;
    }
}

// ---------------------------------------------------------------------------
// K4b: loss (sim symmetric => ce_row == ce_col => loss = row CE).
// 1 block, 64 threads.
// ---------------------------------------------------------------------------
__global__ void k_loss(float* __restrict__ loss_out) {
    const int i = threadIdx.x;  // 0..63
    __shared__ float s_l[64];
    float m = -1e30f;
    #pragma unroll 8
    for (int j = 0; j < B_; ++j) m = fmaxf(m, g_sim[i * B_ + j]);
    float s = 0.f;
    #pragma unroll 8
    for (int j = 0; j < B_; ++j) s += expf(g_sim[i * B_ + j] - m);
    float lse = m + logf(s);
    s_l[i] = lse - g_sim[i * B_ + i];
    __syncthreads();
    if (i == 0) {
        float tot = 0.f;
        #pragma unroll
        for (int j = 0; j < B_; ++j) tot += s_l[j];
        *loss_out = tot * (1.0f / B_);
    }
}

// ---------------------------------------------------------------------------
// K5a: per-row inclusive scan of placeholder mask -> rank (or -1).
// grid=64, 512 threads.
// ---------------------------------------------------------------------------
__global__ void k_rank(const int* __restrict__ ids,
                       const int* __restrict__ ph_ptr) {
    const int b = blockIdx.x, s = threadIdx.x;
    const int ph = *ph_ptr;
    __shared__ int sc[S_];
    const int m = (ids[b * S_ + s] == ph) ? 1 : 0;
    sc[s] = m;
    __syncthreads();
    for (int off = 1; off < S_; off <<= 1) {
        int v = (s >= off) ? sc[s - off] : 0;
        __syncthreads();
        sc[s] += v;
        __syncthreads();
    }
    const int rank = sc[s] - 1;
    g_rank[b * S_ + s] = (m && rank < NSEG) ? rank : -1;
}

// ---------------------------------------------------------------------------
// K5b: text_emb: copy either seg_means[b,rank] or wte[id].  grid=B*S, 192 thr.
// ---------------------------------------------------------------------------
__global__ void k_emb(const float* __restrict__ wte,
                      const int* __restrict__ ids,
                      float* __restrict__ out) {
    const int blk = blockIdx.x;   // b*512 + s
    const int t = threadIdx.x;    // 0..191 (float4)
    const int r = g_rank[blk];
    const float* src;
    if (r >= 0) {
        int b = blk >> 9;
        src = g_C + (size_t)(b * NSEG + r) * DT;
    } else {
        int id = ids[blk];
        src = wte + (size_t)id * DT;
    }
    ((float4*)(out + (size_t)blk * DT))[t] = ((const float4*)src)[t];
}

// ---------------------------------------------------------------------------
extern "C" void kernel_launch(void* const* d_in, const int* in_sizes, int n_in,
                              void* d_out, int out_size) {
    const float* vis   = (const float*)d_in[0];  // [64,256,1024]
    const float* gamma = (const float*)d_in[1];  // [1024]
    const float* beta  = (const float*)d_in[2];  // [1024]
    const float* Wp    = (const float*)d_in[3];  // [1024,768]
    const float* bp    = (const float*)d_in[4];  // [768]
    const float* wte   = (const float*)d_in[5];  // [50257,768]
    const int*   ids   = (const int*)d_in[6];    // [64,512]
    const int*   ph    = (const int*)d_in[7];    // scalar

    float* out = (float*)d_out;
    // layout: text_emb [B*S*Dt] then loss scalar (last element)
    float* loss_out = out + (out_size - 1);

    k_rank<<<B_, S_>>>(ids, ph);
    k_ln_seg<<<M_, 256>>>(vis, gamma, beta);
    {
        dim3 grid(DT / BN, M_ / BM);
        k_gemm<<<grid, 256>>>(Wp, bp);
    }
    k_pool<<<B_, 192>>>();
    {
        dim3 grid(B_, 4);
        k_sim<<<grid, 256>>>();
    }
    k_loss<<<1, 64>>>(loss_out);
    k_emb<<<B_ * S_, 192>>>(wte, ids, out);
}

// round 8
// speedup vs baseline: 1.3134x; 1.1714x over previous
#include <cuda_runtime.h>
#include <cuda_bf16.h>
#include <math.h>

// Problem constants (fixed by setup_inputs)
#define B_   64
#define P_   256
#define DV   1024
#define DT   768
#define S_   512
#define NSEG 32
#define PPT  8
#define M_   (B_ * NSEG)   // 2048 GEMM rows
#define EPSV 1e-5f
#define INV_TEMP (1.0f / 0.07f)

// Scratch (device globals; no allocations allowed)
__device__ float g_A[M_ * DV];        // seg-averaged normalized features  [2048,1024]
__device__ float g_C[M_ * DT];        // seg_means = A @ W + b             [2048,768]
__device__ float g_pool[B_ * DT];     // pooled (mean over segs)           [64,768]
__device__ float g_sim[B_ * B_];      // RAW pooled dot products           [64,64]
__device__ int   g_rank[B_ * S_];     // placeholder rank or -1            [64,512]

// ---- packed f32x2 helpers (Blackwell FFMA2 path) --------------------------
__device__ __forceinline__ unsigned long long pack2(float x, float y) {
    unsigned long long r;
    asm("mov.b64 %0, {%1, %2};" : "=l"(r) : "f"(x), "f"(y));
    return r;
}
__device__ __forceinline__ void unpack2(unsigned long long v, float& x, float& y) {
    asm("mov.b64 {%0, %1}, %2;" : "=f"(x), "=f"(y) : "l"(v));
}
__device__ __forceinline__ unsigned long long fma2(unsigned long long a,
                                                   unsigned long long b,
                                                   unsigned long long c) {
    unsigned long long d;
    asm("fma.rn.f32x2 %0, %1, %2, %3;" : "=l"(d) : "l"(a), "l"(b), "l"(c));
    return d;
}

// ---------------------------------------------------------------------------
// K1: per-(b,seg) block. Preload all 8 patch rows (MLP=8), LayerNorm each,
// accumulate; write A = gamma * (sum xhat / 8) + beta.  grid=2048, 256 thr.
// ---------------------------------------------------------------------------
__global__ void k_ln_seg(const float* __restrict__ x,
                         const float* __restrict__ gamma,
                         const float* __restrict__ beta) {
    const int blk = blockIdx.x;            // b*32 + seg
    const int b = blk >> 5, seg = blk & 31;
    const int t = threadIdx.x;             // 0..255, one float4 per row
    const int wid = t >> 5, lane = t & 31;

    __shared__ float s_s[8][8], s_q[8][8];
    __shared__ float2 s_mi[8];

    const float* base = x + ((size_t)(b * P_ + seg * PPT)) * DV;

    float4 v[8];
    #pragma unroll
    for (int pp = 0; pp < PPT; ++pp)
        v[pp] = ((const float4*)(base + (size_t)pp * DV))[t];

    #pragma unroll
    for (int pp = 0; pp < PPT; ++pp) {
        float s  = v[pp].x + v[pp].y + v[pp].z + v[pp].w;
        float sq = v[pp].x * v[pp].x + v[pp].y * v[pp].y
                 + v[pp].z * v[pp].z + v[pp].w * v[pp].w;
        #pragma unroll
        for (int off = 16; off > 0; off >>= 1) {
            s  += __shfl_down_sync(0xffffffffu, s,  off);
            sq += __shfl_down_sync(0xffffffffu, sq, off);
        }
        if (lane == 0) { s_s[pp][wid] = s; s_q[pp][wid] = sq; }
    }
    __syncthreads();

    // warp `wid` reduces the 8 partials for patch row `wid`
    if (lane < 8) {
        float s = s_s[wid][lane];
        float q = s_q[wid][lane];
        #pragma unroll
        for (int off = 4; off > 0; off >>= 1) {
            s += __shfl_down_sync(0x000000ffu, s, off);
            q += __shfl_down_sync(0x000000ffu, q, off);
        }
        if (lane == 0) {
            float mean = s * (1.0f / DV);
            float var  = q * (1.0f / DV) - mean * mean;
            s_mi[wid] = make_float2(mean, rsqrtf(var + EPSV));
        }
    }
    __syncthreads();

    float4 acc = make_float4(0.f, 0.f, 0.f, 0.f);
    #pragma unroll
    for (int pp = 0; pp < PPT; ++pp) {
        const float2 mi = s_mi[pp];
        acc.x += (v[pp].x - mi.x) * mi.y;
        acc.y += (v[pp].y - mi.x) * mi.y;
        acc.z += (v[pp].z - mi.x) * mi.y;
        acc.w += (v[pp].w - mi.x) * mi.y;
    }

    const float4 g  = ((const float4*)gamma)[t];
    const float4 bb = ((const float4*)beta)[t];
    float4 o;
    o.x = g.x * acc.x * 0.125f + bb.x;
    o.y = g.y * acc.y * 0.125f + bb.y;
    o.z = g.z * acc.z * 0.125f + bb.z;
    o.w = g.w * acc.w * 0.125f + bb.w;
    ((float4*)(g_A + (size_t)blk * DV))[t] = o;
}

// ---------------------------------------------------------------------------
// K2: GEMM  C[2048,768] = A[2048,1024] @ W[1024,768] + bias, fused pooling.
// BM=128 (= 4 batches x 32 segs), BN=64, BK=16, 256 threads, FFMA2 accums,
// double-buffered smem. Epilogue reduces each block's 4 batches x 64 cols
// into g_pool (each (b,col) owned by exactly one block -> no global atomics).
// grid = (768/64, 2048/128) = (12,16) = 192 blocks.
// ---------------------------------------------------------------------------
#define BM 128
#define BN 64
#define BK 16
__global__ void __launch_bounds__(256, 2)
k_gemm(const float* __restrict__ W, const float* __restrict__ bias) {
    __shared__ __align__(16) float As[2][BK][BM];
    __shared__ __align__(16) float Bs[2][BK][BN];
    __shared__ float s_pool[4][BN];

    const int bm = blockIdx.y * BM;
    const int bn = blockIdx.x * BN;
    const int tid = threadIdx.x;          // 256
    const int tx = tid & 15;              // 0..15 -> 4 cols each
    const int ty = tid >> 4;              // 0..15 -> 8 rows each (4 pairs)

    ((float*)s_pool)[tid] = 0.f;          // 4*64 = 256 entries

    // A staging: idx = tid + l*256 -> float4 index 0..511
    const int ar0 = (tid) >> 2,        ac0 = (tid) & 3;
    const int ar1 = (tid + 256) >> 2,  ac1 = (tid + 256) & 3;
    // B staging
    const int brow = tid >> 4, bcol = tid & 15;

    unsigned long long acc[4][4];         // [row-pair][col], 32 floats
    #pragma unroll
    for (int i = 0; i < 4; ++i)
        #pragma unroll
        for (int j = 0; j < 4; ++j) acc[i][j] = 0ull;

    float4 va0, va1, vb;
    // prefetch tile 0
    va0 = *(const float4*)(g_A + (size_t)(bm + ar0) * DV + ac0 * 4);
    va1 = *(const float4*)(g_A + (size_t)(bm + ar1) * DV + ac1 * 4);
    vb  = *(const float4*)(W + (size_t)brow * DT + bn + bcol * 4);
    {
        As[0][ac0 * 4 + 0][ar0] = va0.x; As[0][ac0 * 4 + 1][ar0] = va0.y;
        As[0][ac0 * 4 + 2][ar0] = va0.z; As[0][ac0 * 4 + 3][ar0] = va0.w;
        As[0][ac1 * 4 + 0][ar1] = va1.x; As[0][ac1 * 4 + 1][ar1] = va1.y;
        As[0][ac1 * 4 + 2][ar1] = va1.z; As[0][ac1 * 4 + 3][ar1] = va1.w;
        *(float4*)&Bs[0][brow][bcol * 4] = vb;
    }
    __syncthreads();

    const int NT = DV / BK;  // 64
    int cur = 0;
    for (int t = 0; t < NT; ++t) {
        const int k0n = (t + 1) * BK;
        if (t + 1 < NT) {
            va0 = *(const float4*)(g_A + (size_t)(bm + ar0) * DV + k0n + ac0 * 4);
            va1 = *(const float4*)(g_A + (size_t)(bm + ar1) * DV + k0n + ac1 * 4);
            vb  = *(const float4*)(W + (size_t)(k0n + brow) * DT + bn + bcol * 4);
        }

        #pragma unroll
        for (int k = 0; k < BK; ++k) {
            unsigned long long a0 = *(const unsigned long long*)&As[cur][k][ty * 8 + 0];
            unsigned long long a1 = *(const unsigned long long*)&As[cur][k][ty * 8 + 2];
            unsigned long long a2 = *(const unsigned long long*)&As[cur][k][ty * 8 + 4];
            unsigned long long a3 = *(const unsigned long long*)&As[cur][k][ty * 8 + 6];
            float4 bv = *(const float4*)&Bs[cur][k][tx * 4];
            unsigned long long b0 = pack2(bv.x, bv.x);
            unsigned long long b1 = pack2(bv.y, bv.y);
            unsigned long long b2 = pack2(bv.z, bv.z);
            unsigned long long b3 = pack2(bv.w, bv.w);
            acc[0][0] = fma2(a0, b0, acc[0][0]);
            acc[0][1] = fma2(a0, b1, acc[0][1]);
            acc[0][2] = fma2(a0, b2, acc[0][2]);
            acc[0][3] = fma2(a0, b3, acc[0][3]);
            acc[1][0] = fma2(a1, b0, acc[1][0]);
            acc[1][1] = fma2(a1, b1, acc[1][1]);
            acc[1][2] = fma2(a1, b2, acc[1][2]);
            acc[1][3] = fma2(a1, b3, acc[1][3]);
            acc[2][0] = fma2(a2, b0, acc[2][0]);
            acc[2][1] = fma2(a2, b1, acc[2][1]);
            acc[2][2] = fma2(a2, b2, acc[2][2]);
            acc[2][3] = fma2(a2, b3, acc[2][3]);
            acc[3][0] = fma2(a3, b0, acc[3][0]);
            acc[3][1] = fma2(a3, b1, acc[3][1]);
            acc[3][2] = fma2(a3, b2, acc[3][2]);
            acc[3][3] = fma2(a3, b3, acc[3][3]);
        }

        if (t + 1 < NT) {
            const int nxt = cur ^ 1;
            As[nxt][ac0 * 4 + 0][ar0] = va0.x; As[nxt][ac0 * 4 + 1][ar0] = va0.y;
            As[nxt][ac0 * 4 + 2][ar0] = va0.z; As[nxt][ac0 * 4 + 3][ar0] = va0.w;
            As[nxt][ac1 * 4 + 0][ar1] = va1.x; As[nxt][ac1 * 4 + 1][ar1] = va1.y;
            As[nxt][ac1 * 4 + 2][ar1] = va1.z; As[nxt][ac1 * 4 + 3][ar1] = va1.w;
            *(float4*)&Bs[nxt][brow][bcol * 4] = vb;
        }
        __syncthreads();
        cur ^= 1;
    }

    const float4 bsv = *(const float4*)(bias + bn + tx * 4);
    float cs0 = 0.f, cs1 = 0.f, cs2 = 0.f, cs3 = 0.f;   // column sums of my 8 rows
    #pragma unroll
    for (int ii = 0; ii < 4; ++ii) {
        float lo0, hi0, lo1, hi1, lo2, hi2, lo3, hi3;
        unpack2(acc[ii][0], lo0, hi0);
        unpack2(acc[ii][1], lo1, hi1);
        unpack2(acc[ii][2], lo2, hi2);
        unpack2(acc[ii][3], lo3, hi3);
        const int m0 = bm + ty * 8 + 2 * ii;
        float4 o0, o1;
        o0.x = lo0 + bsv.x; o0.y = lo1 + bsv.y; o0.z = lo2 + bsv.z; o0.w = lo3 + bsv.w;
        o1.x = hi0 + bsv.x; o1.y = hi1 + bsv.y; o1.z = hi2 + bsv.z; o1.w = hi3 + bsv.w;
        *(float4*)(g_C + (size_t)m0 * DT + bn + tx * 4) = o0;
        *(float4*)(g_C + (size_t)(m0 + 1) * DT + bn + tx * 4) = o1;
        cs0 += o0.x + o1.x; cs1 += o0.y + o1.y;
        cs2 += o0.z + o1.z; cs3 += o0.w + o1.w;
    }

    // fused pooling: my 8 rows all belong to batch-slot (ty>>2) of this block
    const int bloc = ty >> 2;
    atomicAdd(&s_pool[bloc][tx * 4 + 0], cs0);
    atomicAdd(&s_pool[bloc][tx * 4 + 1], cs1);
    atomicAdd(&s_pool[bloc][tx * 4 + 2], cs2);
    atomicAdd(&s_pool[bloc][tx * 4 + 3], cs3);
    __syncthreads();
    {
        const int bl = tid >> 6, col = tid & 63;   // 4 x 64 = 256
        g_pool[(size_t)(blockIdx.y * 4 + bl) * DT + bn + col] =
            s_pool[bl][col] * (1.0f / NSEG);
    }
}

// ---------------------------------------------------------------------------
// K3: raw dots d[i][j] = pooled_i . pooled_j. grid=(64,4), 256 threads.
// Normalization deferred to k_tail (scale-invariant).
// ---------------------------------------------------------------------------
__global__ void k_sim(void) {
    const int i = blockIdx.x;
    const int wid = threadIdx.x >> 5, lane = threadIdx.x & 31;
    const float4* Ri = (const float4*)(g_pool + (size_t)i * DT);
    float4 ri[6];
    #pragma unroll
    for (int c = 0; c < 6; ++c) ri[c] = Ri[lane + 32 * c];

    #pragma unroll
    for (int jj = 0; jj < 2; ++jj) {
        const int j = blockIdx.y * 16 + wid * 2 + jj;
        const float4* Rj = (const float4*)(g_pool + (size_t)j * DT);
        float s = 0.f;
        #pragma unroll
        for (int c = 0; c < 6; ++c) {
            float4 r = Rj[lane + 32 * c];
            s = fmaf(ri[c].x, r.x, s);
            s = fmaf(ri[c].y, r.y, s);
            s = fmaf(ri[c].z, r.z, s);
            s = fmaf(ri[c].w, r.w, s);
        }
        #pragma unroll
        for (int off = 16; off > 0; off >>= 1)
            s += __shfl_down_sync(0xffffffffu, s, off);
        if (lane == 0) g_sim[i * B_ + j] = s;
    }
}

// ---------------------------------------------------------------------------
// K4: tail. Block 0 = contrastive loss (normalize raw dots on the fly;
// sim symmetric => loss = row CE). Blocks 1..64 = per-row placeholder rank
// scan. 512 threads/block.
// ---------------------------------------------------------------------------
__global__ void k_tail(const int* __restrict__ ids,
                       const int* __restrict__ ph_ptr,
                       float* __restrict__ loss_out) {
    if (blockIdx.x == 0) {
        const int i = threadIdx.x;  // use first 64 threads
        __shared__ float s_inv[B_];
        __shared__ float s_l[B_];
        if (i < B_) s_inv[i] = rsqrtf(g_sim[i * B_ + i]);
        __syncthreads();
        if (i < B_) {
            const float invi = s_inv[i];
            float m = -1e30f, vii = 0.f;
            #pragma unroll 8
            for (int j = 0; j < B_; ++j) {
                float v = g_sim[i * B_ + j] * invi * s_inv[j] * INV_TEMP;
                m = fmaxf(m, v);
                if (j == i) vii = v;
            }
            float s = 0.f;
            #pragma unroll 8
            for (int j = 0; j < B_; ++j) {
                float v = g_sim[i * B_ + j] * invi * s_inv[j] * INV_TEMP;
                s += expf(v - m);
            }
            s_l[i] = m + logf(s) - vii;
        }
        __syncthreads();
        if (i == 0) {
            float tot = 0.f;
            #pragma unroll
            for (int j = 0; j < B_; ++j) tot += s_l[j];
            *loss_out = tot * (1.0f / B_);
        }
    } else {
        const int b = blockIdx.x - 1, s = threadIdx.x;  // 512 threads
        const int ph = *ph_ptr;
        __shared__ int sc[S_];
        const int m = (ids[b * S_ + s] == ph) ? 1 : 0;
        sc[s] = m;
        __syncthreads();
        for (int off = 1; off < S_; off <<= 1) {
            int v = (s >= off) ? sc[s - off] : 0;
            __syncthreads();
            sc[s] += v;
            __syncthreads();
        }
        const int rank = sc[s] - 1;
        g_rank[b * S_ + s] = (m && rank < NSEG) ? rank : -1;
    }
}

// ---------------------------------------------------------------------------
// K5: text_emb: copy either seg_means[b,rank] or wte[id].  grid=B*S, 192 thr.
// ---------------------------------------------------------------------------
__global__ void k_emb(const float* __restrict__ wte,
                      const int* __restrict__ ids,
                      float* __restrict__ out) {
    const int blk = blockIdx.x;   // b*512 + s
    const int t = threadIdx.x;    // 0..191 (float4)
    const int r = g_rank[blk];
    const float* src;
    if (r >= 0) {
        int b = blk >> 9;
        src = g_C + (size_t)(b * NSEG + r) * DT;
    } else {
        int id = ids[blk];
        src = wte + (size_t)id * DT;
    }
    ((float4*)(out + (size_t)blk * DT))[t] = ((const float4*)src)[t];
}

// ---------------------------------------------------------------------------
extern "C" void kernel_launch(void* const* d_in, const int* in_sizes, int n_in,
                              void* d_out, int out_size) {
    const float* vis   = (const float*)d_in[0];  // [64,256,1024]
    const float* gamma = (const float*)d_in[1];  // [1024]
    const float* beta  = (const float*)d_in[2];  // [1024]
    const float* Wp    = (const float*)d_in[3];  // [1024,768]
    const float* bp    = (const float*)d_in[4];  // [768]
    const float* wte   = (const float*)d_in[5];  // [50257,768]
    const int*   ids   = (const int*)d_in[6];    // [64,512]
    const int*   ph    = (const int*)d_in[7];    // scalar

    float* out = (float*)d_out;
    // layout: text_emb [B*S*Dt] then loss scalar (last element)
    float* loss_out = out + (out_size - 1);

    k_ln_seg<<<M_, 256>>>(vis, gamma, beta);
    {
        dim3 grid(DT / BN, M_ / BM);
        k_gemm<<<grid, 256>>>(Wp, bp);
    }
    {
        dim3 grid(B_, 4);
        k_sim<<<grid, 256>>>();
    }
    k_tail<<<1 + B_, 512>>>(ids, ph, loss_out);
    k_emb<<<B_ * S_, 192>>>(wte, ids, out);
}

// round 10
// speedup vs baseline: 1.3169x; 1.0026x over previous
#include <cuda_runtime.h>
#include <cuda_bf16.h>
#include <math.h>

// Problem constants (fixed by setup_inputs)
#define B_   64
#define P_   256
#define DV   1024
#define DT   768
#define S_   512
#define NSEG 32
#define PPT  8
#define M_   (B_ * NSEG)   // 2048 GEMM rows
#define EPSV 1e-5f
#define INV_TEMP (1.0f / 0.07f)

// Scratch (device globals; no allocations allowed)
__device__ float g_A[M_ * DV];        // seg-averaged normalized features  [2048,1024]
__device__ float g_C[M_ * DT];        // seg_means = A @ W + b             [2048,768]
__device__ float g_pool[B_ * DT];     // pooled (mean over segs)           [64,768]
__device__ float g_rowloss[B_];       // per-row CE terms

// ---- packed f32x2 helpers (Blackwell FFMA2 path) --------------------------
__device__ __forceinline__ unsigned long long pack2(float x, float y) {
    unsigned long long r;
    asm("mov.b64 %0, {%1, %2};" : "=l"(r) : "f"(x), "f"(y));
    return r;
}
__device__ __forceinline__ void unpack2(unsigned long long v, float& x, float& y) {
    asm("mov.b64 {%0, %1}, %2;" : "=f"(x), "=f"(y) : "l"(v));
}
__device__ __forceinline__ unsigned long long fma2(unsigned long long a,
                                                   unsigned long long b,
                                                   unsigned long long c) {
    unsigned long long d;
    asm("fma.rn.f32x2 %0, %1, %2, %3;" : "=l"(d) : "l"(a), "l"(b), "l"(c));
    return d;
}

// ---------------------------------------------------------------------------
// K1: per-(b,seg) block. Preload all 8 patch rows (MLP=8), LayerNorm each,
// accumulate; write A = gamma * (sum xhat / 8) + beta.  grid=2048, 256 thr.
// ---------------------------------------------------------------------------
__global__ void k_ln_seg(const float* __restrict__ x,
                         const float* __restrict__ gamma,
                         const float* __restrict__ beta) {
    const int blk = blockIdx.x;            // b*32 + seg
    const int b = blk >> 5, seg = blk & 31;
    const int t = threadIdx.x;             // 0..255, one float4 per row
    const int wid = t >> 5, lane = t & 31;

    __shared__ float s_s[8][8], s_q[8][8];
    __shared__ float2 s_mi[8];

    const float* base = x + ((size_t)(b * P_ + seg * PPT)) * DV;

    float4 v[8];
    #pragma unroll
    for (int pp = 0; pp < PPT; ++pp)
        v[pp] = ((const float4*)(base + (size_t)pp * DV))[t];

    #pragma unroll
    for (int pp = 0; pp < PPT; ++pp) {
        float s  = v[pp].x + v[pp].y + v[pp].z + v[pp].w;
        float sq = v[pp].x * v[pp].x + v[pp].y * v[pp].y
                 + v[pp].z * v[pp].z + v[pp].w * v[pp].w;
        #pragma unroll
        for (int off = 16; off > 0; off >>= 1) {
            s  += __shfl_down_sync(0xffffffffu, s,  off);
            sq += __shfl_down_sync(0xffffffffu, sq, off);
        }
        if (lane == 0) { s_s[pp][wid] = s; s_q[pp][wid] = sq; }
    }
    __syncthreads();

    if (lane < 8) {
        float s = s_s[wid][lane];
        float q = s_q[wid][lane];
        #pragma unroll
        for (int off = 4; off > 0; off >>= 1) {
            s += __shfl_down_sync(0x000000ffu, s, off);
            q += __shfl_down_sync(0x000000ffu, q, off);
        }
        if (lane == 0) {
            float mean = s * (1.0f / DV);
            float var  = q * (1.0f / DV) - mean * mean;
            s_mi[wid] = make_float2(mean, rsqrtf(var + EPSV));
        }
    }
    __syncthreads();

    float4 acc = make_float4(0.f, 0.f, 0.f, 0.f);
    #pragma unroll
    for (int pp = 0; pp < PPT; ++pp) {
        const float2 mi = s_mi[pp];
        acc.x += (v[pp].x - mi.x) * mi.y;
        acc.y += (v[pp].y - mi.x) * mi.y;
        acc.z += (v[pp].z - mi.x) * mi.y;
        acc.w += (v[pp].w - mi.x) * mi.y;
    }

    const float4 g  = ((const float4*)gamma)[t];
    const float4 bb = ((const float4*)beta)[t];
    float4 o;
    o.x = g.x * acc.x * 0.125f + bb.x;
    o.y = g.y * acc.y * 0.125f + bb.y;
    o.z = g.z * acc.z * 0.125f + bb.z;
    o.w = g.w * acc.w * 0.125f + bb.w;
    ((float4*)(g_A + (size_t)blk * DV))[t] = o;
}

// ---------------------------------------------------------------------------
// K2: GEMM  C[2048,768] = A[2048,1024] @ W[1024,768] + bias, fused pooling.
// BM=128 (= 4 batches x 32 segs), BN=96, BK=16, 256 threads, FFMA2 accums,
// double-buffered smem. grid = (768/96, 2048/128) = (8,16) = 128 blocks
// -> ONE balanced wave on 148 SMs (no wave-quantization tail).
// ---------------------------------------------------------------------------
#define BM 128
#define BN 96
#define BK 16
__global__ void __launch_bounds__(256, 1)
k_gemm(const float* __restrict__ W, const float* __restrict__ bias) {
    __shared__ __align__(16) float As[2][BK][BM];
    __shared__ __align__(16) float Bs[2][BK][BN];
    __shared__ float s_pool[4][BN];

    const int bm = blockIdx.y * BM;
    const int bn = blockIdx.x * BN;
    const int tid = threadIdx.x;          // 256
    const int tx = tid & 15;              // col group: 6 cols each
    const int ty = tid >> 4;              // row group: 8 rows each (4 pairs)

    for (int idx = tid; idx < 4 * BN; idx += 256)
        ((float*)s_pool)[idx] = 0.f;

    // A staging: 512 float4 per tile, 2 per thread
    const int ar0 = tid >> 2,          ac0 = tid & 3;
    const int ar1 = (tid + 256) >> 2,  ac1 = (tid + 256) & 3;
    // B staging: 16 rows x 24 float4 = 384 float4
    const int br0 = tid / 24,  bc0 = tid % 24;
    const int br1 = (tid + 256) / 24, bc1 = (tid + 256) % 24;
    const bool bv1 = (tid + 256) < 384;

    unsigned long long acc[4][6];
    #pragma unroll
    for (int i = 0; i < 4; ++i)
        #pragma unroll
        for (int j = 0; j < 6; ++j) acc[i][j] = 0ull;

    float4 va0, va1, vb0, vb1;
    va0 = *(const float4*)(g_A + (size_t)(bm + ar0) * DV + ac0 * 4);
    va1 = *(const float4*)(g_A + (size_t)(bm + ar1) * DV + ac1 * 4);
    vb0 = *(const float4*)(W + (size_t)br0 * DT + bn + bc0 * 4);
    if (bv1) vb1 = *(const float4*)(W + (size_t)br1 * DT + bn + bc1 * 4);
    {
        As[0][ac0 * 4 + 0][ar0] = va0.x; As[0][ac0 * 4 + 1][ar0] = va0.y;
        As[0][ac0 * 4 + 2][ar0] = va0.z; As[0][ac0 * 4 + 3][ar0] = va0.w;
        As[0][ac1 * 4 + 0][ar1] = va1.x; As[0][ac1 * 4 + 1][ar1] = va1.y;
        As[0][ac1 * 4 + 2][ar1] = va1.z; As[0][ac1 * 4 + 3][ar1] = va1.w;
        *(float4*)&Bs[0][br0][bc0 * 4] = vb0;
        if (bv1) *(float4*)&Bs[0][br1][bc1 * 4] = vb1;
    }
    __syncthreads();

    const int NT = DV / BK;  // 64
    int cur = 0;
    for (int t = 0; t < NT; ++t) {
        const int k0n = (t + 1) * BK;
        if (t + 1 < NT) {
            va0 = *(const float4*)(g_A + (size_t)(bm + ar0) * DV + k0n + ac0 * 4);
            va1 = *(const float4*)(g_A + (size_t)(bm + ar1) * DV + k0n + ac1 * 4);
            vb0 = *(const float4*)(W + (size_t)(k0n + br0) * DT + bn + bc0 * 4);
            if (bv1) vb1 = *(const float4*)(W + (size_t)(k0n + br1) * DT + bn + bc1 * 4);
        }

        #pragma unroll
        for (int k = 0; k < BK; ++k) {
            unsigned long long a0 = *(const unsigned long long*)&As[cur][k][ty * 8 + 0];
            unsigned long long a1 = *(const unsigned long long*)&As[cur][k][ty * 8 + 2];
            unsigned long long a2 = *(const unsigned long long*)&As[cur][k][ty * 8 + 4];
            unsigned long long a3 = *(const unsigned long long*)&As[cur][k][ty * 8 + 6];
            float2 q0 = *(const float2*)&Bs[cur][k][tx * 6 + 0];
            float2 q1 = *(const float2*)&Bs[cur][k][tx * 6 + 2];
            float2 q2 = *(const float2*)&Bs[cur][k][tx * 6 + 4];
            unsigned long long b0 = pack2(q0.x, q0.x);
            unsigned long long b1 = pack2(q0.y, q0.y);
            unsigned long long b2 = pack2(q1.x, q1.x);
            unsigned long long b3 = pack2(q1.y, q1.y);
            unsigned long long b4 = pack2(q2.x, q2.x);
            unsigned long long b5 = pack2(q2.y, q2.y);
            #pragma unroll
            for (int ii = 0; ii < 4; ++ii) {
                unsigned long long a = (ii == 0) ? a0 : (ii == 1) ? a1 : (ii == 2) ? a2 : a3;
                acc[ii][0] = fma2(a, b0, acc[ii][0]);
                acc[ii][1] = fma2(a, b1, acc[ii][1]);
                acc[ii][2] = fma2(a, b2, acc[ii][2]);
                acc[ii][3] = fma2(a, b3, acc[ii][3]);
                acc[ii][4] = fma2(a, b4, acc[ii][4]);
                acc[ii][5] = fma2(a, b5, acc[ii][5]);
            }
        }

        if (t + 1 < NT) {
            const int nxt = cur ^ 1;
            As[nxt][ac0 * 4 + 0][ar0] = va0.x; As[nxt][ac0 * 4 + 1][ar0] = va0.y;
            As[nxt][ac0 * 4 + 2][ar0] = va0.z; As[nxt][ac0 * 4 + 3][ar0] = va0.w;
            As[nxt][ac1 * 4 + 0][ar1] = va1.x; As[nxt][ac1 * 4 + 1][ar1] = va1.y;
            As[nxt][ac1 * 4 + 2][ar1] = va1.z; As[nxt][ac1 * 4 + 3][ar1] = va1.w;
            *(float4*)&Bs[nxt][br0][bc0 * 4] = vb0;
            if (bv1) *(float4*)&Bs[nxt][br1][bc1 * 4] = vb1;
        }
        __syncthreads();
        cur ^= 1;
    }

    // epilogue: bias add, C store, fused pooling
    float b6[6];
    {
        float2 u0 = *(const float2*)(bias + bn + tx * 6 + 0);
        float2 u1 = *(const float2*)(bias + bn + tx * 6 + 2);
        float2 u2 = *(const float2*)(bias + bn + tx * 6 + 4);
        b6[0] = u0.x; b6[1] = u0.y; b6[2] = u1.x;
        b6[3] = u1.y; b6[4] = u2.x; b6[5] = u2.y;
    }
    float cs[6] = {0.f, 0.f, 0.f, 0.f, 0.f, 0.f};
    #pragma unroll
    for (int ii = 0; ii < 4; ++ii) {
        float lo[6], hi[6];
        #pragma unroll
        for (int c = 0; c < 6; ++c) {
            unpack2(acc[ii][c], lo[c], hi[c]);
            lo[c] += b6[c]; hi[c] += b6[c];
            cs[c] += lo[c] + hi[c];
        }
        const int m0 = bm + ty * 8 + 2 * ii;
        float* p0 = g_C + (size_t)m0 * DT + bn + tx * 6;
        float* p1 = g_C + (size_t)(m0 + 1) * DT + bn + tx * 6;
        *(float2*)(p0 + 0) = make_float2(lo[0], lo[1]);
        *(float2*)(p0 + 2) = make_float2(lo[2], lo[3]);
        *(float2*)(p0 + 4) = make_float2(lo[4], lo[5]);
        *(float2*)(p1 + 0) = make_float2(hi[0], hi[1]);
        *(float2*)(p1 + 2) = make_float2(hi[2], hi[3]);
        *(float2*)(p1 + 4) = make_float2(hi[4], hi[5]);
    }
    const int bloc = ty >> 2;  // batch slot 0..3 (32 rows each)
    #pragma unroll
    for (int c = 0; c < 6; ++c)
        atomicAdd(&s_pool[bloc][tx * 6 + c], cs[c]);
    __syncthreads();
    for (int idx = tid; idx < 4 * BN; idx += 256) {
        const int bl = idx / BN, col = idx % BN;
        g_pool[(size_t)(blockIdx.y * 4 + bl) * DT + bn + col] =
            s_pool[bl][col] * (1.0f / NSEG);
    }
}

// ---------------------------------------------------------------------------
// K3: per-row sim + CE term. 64 blocks x 256 threads.
// Block i computes sim row i AND all diagonals (free on same rj loads).
// Row-loss computed by thread 0 with SEQUENTIAL j-loops (round-8 numerics:
// the loss ~= log1p(sum of tiny exps) is summation-order sensitive; the
// tree-reduction variant moved rel_err 8.4e-4 -> 2.6e-3).
// ---------------------------------------------------------------------------
__global__ void k_post(void) {
    const int i = blockIdx.x;
    const int tid = threadIdx.x;
    const int wid = tid >> 5, lane = tid & 31;
    __shared__ float s_sim[B_], s_diag[B_];

    const float4* Ri = (const float4*)(g_pool + (size_t)i * DT);
    float4 ri[6];
    #pragma unroll
    for (int c = 0; c < 6; ++c) ri[c] = Ri[lane + 32 * c];

    #pragma unroll
    for (int jj = 0; jj < 8; ++jj) {
        const int j = wid * 8 + jj;
        const float4* Rj = (const float4*)(g_pool + (size_t)j * DT);
        float sij = 0.f, sjj = 0.f;
        #pragma unroll
        for (int c = 0; c < 6; ++c) {
            float4 r = Rj[lane + 32 * c];
            sij = fmaf(ri[c].x, r.x, sij); sjj = fmaf(r.x, r.x, sjj);
            sij = fmaf(ri[c].y, r.y, sij); sjj = fmaf(r.y, r.y, sjj);
            sij = fmaf(ri[c].z, r.z, sij); sjj = fmaf(r.z, r.z, sjj);
            sij = fmaf(ri[c].w, r.w, sij); sjj = fmaf(r.w, r.w, sjj);
        }
        #pragma unroll
        for (int off = 16; off > 0; off >>= 1) {
            sij += __shfl_down_sync(0xffffffffu, sij, off);
            sjj += __shfl_down_sync(0xffffffffu, sjj, off);
        }
        if (lane == 0) { s_sim[j] = sij; s_diag[j] = sjj; }
    }
    __syncthreads();

    if (tid == 0) {
        const float invi = rsqrtf(s_diag[i]);
        float m = -1e30f, vii = 0.f;
        #pragma unroll 8
        for (int j = 0; j < B_; ++j) {
            float v = s_sim[j] * invi * rsqrtf(s_diag[j]) * INV_TEMP;
            m = fmaxf(m, v);
            if (j == i) vii = v;
        }
        float s = 0.f;
        #pragma unroll 8
        for (int j = 0; j < B_; ++j) {
            float v = s_sim[j] * invi * rsqrtf(s_diag[j]) * INV_TEMP;
            s += expf(v - m);
        }
        g_rowloss[i] = m + logf(s) - vii;
    }
}

// ---------------------------------------------------------------------------
// K4: rank (ballot scan) + text_emb gather/copy.  grid=512 (b*8+chunk),
// 512 threads. Block 0 also reduces g_rowloss -> loss output.
// ---------------------------------------------------------------------------
__global__ void __launch_bounds__(512, 2)
k_emb(const float* __restrict__ wte,
      const int* __restrict__ ids,
      const int* __restrict__ ph_ptr,
      float* __restrict__ out,
      float* __restrict__ loss_out) {
    const int b = blockIdx.x >> 3;
    const int c = blockIdx.x & 7;     // 64-token chunk within the row
    const int tid = threadIdx.x;      // 0..511

    __shared__ int s_ids[S_];
    __shared__ unsigned s_bal[16];
    __shared__ const float* s_src[64];

    const int ph = *ph_ptr;
    const int id = ids[b * S_ + tid];
    s_ids[tid] = id;
    const unsigned bal = __ballot_sync(0xffffffffu, id == ph);
    if ((tid & 31) == 0) s_bal[tid >> 5] = bal;
    __syncthreads();

    if (tid < 64) {
        const int s = c * 64 + tid;
        const int g = s >> 5, l = s & 31;
        int pre = 0;
        for (int gg = 0; gg < g; ++gg) pre += __popc(s_bal[gg]);
        const unsigned bg = s_bal[g];
        const int incl = pre + __popc(bg & (0xffffffffu >> (31 - l)));
        const bool isph = (s_ids[s] == ph);
        const int r = incl - 1;
        s_src[tid] = (isph && r < NSEG)
                   ? (g_C + (size_t)(b * NSEG + r) * DT)
                   : (wte + (size_t)s_ids[s] * DT);
    }
    __syncthreads();

    float4* dst = (float4*)(out + ((size_t)(b * S_ + c * 64)) * DT);
    #pragma unroll 4
    for (int idx = tid; idx < 64 * (DT / 4); idx += 512) {
        const int u = idx / (DT / 4);
        const int q = idx - u * (DT / 4);
        dst[idx] = ((const float4*)s_src[u])[q];
    }

    if (blockIdx.x == 0 && tid == 0) {
        float t = 0.f;
        #pragma unroll
        for (int j = 0; j < B_; ++j) t += g_rowloss[j];
        *loss_out = t * (1.0f / B_);
    }
}

// ---------------------------------------------------------------------------
extern "C" void kernel_launch(void* const* d_in, const int* in_sizes, int n_in,
                              void* d_out, int out_size) {
    const float* vis   = (const float*)d_in[0];  // [64,256,1024]
    const float* gamma = (const float*)d_in[1];  // [1024]
    const float* beta  = (const float*)d_in[2];  // [1024]
    const float* Wp    = (const float*)d_in[3];  // [1024,768]
    const float* bp    = (const float*)d_in[4];  // [768]
    const float* wte   = (const float*)d_in[5];  // [50257,768]
    const int*   ids   = (const int*)d_in[6];    // [64,512]
    const int*   ph    = (const int*)d_in[7];    // scalar

    float* out = (float*)d_out;
    float* loss_out = out + (out_size - 1);

    k_ln_seg<<<M_, 256>>>(vis, gamma, beta);
    {
        dim3 grid(DT / BN, M_ / BM);
        k_gemm<<<grid, 256>>>(Wp, bp);
    }
    k_post<<<B_, 256>>>();
    k_emb<<<B_ * 8, 512>>>(wte, ids, ph, out, loss_out);
}

// round 13
// speedup vs baseline: 1.3375x; 1.0157x over previous
#include <cuda_runtime.h>
#include <cuda_bf16.h>
#include <math.h>

// Problem constants (fixed by setup_inputs)
#define B_   64
#define P_   256
#define DV   1024
#define DT   768
#define S_   512
#define NSEG 32
#define PPT  8
#define M_   (B_ * NSEG)   // 2048 GEMM rows
#define EPSV 1e-5f
#define INV_TEMP (1.0 / 0.07)

// Scratch (device globals; no allocations allowed)
__device__ float  g_A[M_ * DV];       // seg-averaged normalized features  [2048,1024]
__device__ float  g_C[M_ * DT];       // seg_means = A @ W + b             [2048,768]
__device__ float  g_pool[B_ * DT];    // pooled (mean over segs)           [64,768]
__device__ double g_rowloss[B_];      // per-row CE terms (double)

// ---- packed f32x2 helpers (Blackwell FFMA2 path) --------------------------
__device__ __forceinline__ unsigned long long pack2(float x, float y) {
    unsigned long long r;
    asm("mov.b64 %0, {%1, %2};" : "=l"(r) : "f"(x), "f"(y));
    return r;
}
__device__ __forceinline__ void unpack2(unsigned long long v, float& x, float& y) {
    asm("mov.b64 {%0, %1}, %2;" : "=f"(x), "=f"(y) : "l"(v));
}
__device__ __forceinline__ unsigned long long fma2(unsigned long long a,
                                                   unsigned long long b,
                                                   unsigned long long c) {
    unsigned long long d;
    asm("fma.rn.f32x2 %0, %1, %2, %3;" : "=l"(d) : "l"(a), "l"(b), "l"(c));
    return d;
}

// ---------------------------------------------------------------------------
// K1: per-(b,seg) block. Preload all 8 patch rows (MLP=8), LayerNorm each,
// accumulate; write A = gamma * (sum xhat / 8) + beta.  grid=2048, 256 thr.
// ---------------------------------------------------------------------------
__global__ void k_ln_seg(const float* __restrict__ x,
                         const float* __restrict__ gamma,
                         const float* __restrict__ beta) {
    const int blk = blockIdx.x;            // b*32 + seg
    const int b = blk >> 5, seg = blk & 31;
    const int t = threadIdx.x;             // 0..255, one float4 per row
    const int wid = t >> 5, lane = t & 31;

    __shared__ float s_s[8][8], s_q[8][8];
    __shared__ float2 s_mi[8];

    const float* base = x + ((size_t)(b * P_ + seg * PPT)) * DV;

    float4 v[8];
    #pragma unroll
    for (int pp = 0; pp < PPT; ++pp)
        v[pp] = ((const float4*)(base + (size_t)pp * DV))[t];

    #pragma unroll
    for (int pp = 0; pp < PPT; ++pp) {
        float s  = v[pp].x + v[pp].y + v[pp].z + v[pp].w;
        float sq = v[pp].x * v[pp].x + v[pp].y * v[pp].y
                 + v[pp].z * v[pp].z + v[pp].w * v[pp].w;
        #pragma unroll
        for (int off = 16; off > 0; off >>= 1) {
            s  += __shfl_down_sync(0xffffffffu, s,  off);
            sq += __shfl_down_sync(0xffffffffu, sq, off);
        }
        if (lane == 0) { s_s[pp][wid] = s; s_q[pp][wid] = sq; }
    }
    __syncthreads();

    if (lane < 8) {
        float s = s_s[wid][lane];
        float q = s_q[wid][lane];
        #pragma unroll
        for (int off = 4; off > 0; off >>= 1) {
            s += __shfl_down_sync(0x000000ffu, s, off);
            q += __shfl_down_sync(0x000000ffu, q, off);
        }
        if (lane == 0) {
            float mean = s * (1.0f / DV);
            float var  = q * (1.0f / DV) - mean * mean;
            s_mi[wid] = make_float2(mean, rsqrtf(var + EPSV));
        }
    }
    __syncthreads();

    float4 acc = make_float4(0.f, 0.f, 0.f, 0.f);
    #pragma unroll
    for (int pp = 0; pp < PPT; ++pp) {
        const float2 mi = s_mi[pp];
        acc.x += (v[pp].x - mi.x) * mi.y;
        acc.y += (v[pp].y - mi.x) * mi.y;
        acc.z += (v[pp].z - mi.x) * mi.y;
        acc.w += (v[pp].w - mi.x) * mi.y;
    }

    const float4 g  = ((const float4*)gamma)[t];
    const float4 bb = ((const float4*)beta)[t];
    float4 o;
    o.x = g.x * acc.x * 0.125f + bb.x;
    o.y = g.y * acc.y * 0.125f + bb.y;
    o.z = g.z * acc.z * 0.125f + bb.z;
    o.w = g.w * acc.w * 0.125f + bb.w;
    ((float4*)(g_A + (size_t)blk * DV))[t] = o;
}

// ---------------------------------------------------------------------------
// K2: GEMM  C[2048,768] = A[2048,1024] @ W[1024,768] + bias, fused pooling.
// BM=128 (= 4 batches x 32 segs), BN=96, BK=16, 256 threads, FFMA2 accums,
// double-buffered smem. grid = (8,16) = 128 blocks -> one wave.
// Pooling epilogue is DETERMINISTIC: per-ty partials + fixed-order 4-way sum
// (no smem atomics -> no scheduling-dependent bits).
// ---------------------------------------------------------------------------
#define BM 128
#define BN 96
#define BK 16
__global__ void __launch_bounds__(256, 1)
k_gemm(const float* __restrict__ W, const float* __restrict__ bias) {
    __shared__ __align__(16) float As[2][BK][BM];
    __shared__ __align__(16) float Bs[2][BK][BN];
    __shared__ float s_part[16][BN];   // per-ty column partials

    const int bm = blockIdx.y * BM;
    const int bn = blockIdx.x * BN;
    const int tid = threadIdx.x;          // 256
    const int tx = tid & 15;              // col group: 6 cols each
    const int ty = tid >> 4;              // row group: 8 rows each (4 pairs)

    const int ar0 = tid >> 2,          ac0 = tid & 3;
    const int ar1 = (tid + 256) >> 2,  ac1 = (tid + 256) & 3;
    const int br0 = tid / 24,  bc0 = tid % 24;
    const int br1 = (tid + 256) / 24, bc1 = (tid + 256) % 24;
    const bool bv1 = (tid + 256) < 384;

    unsigned long long acc[4][6];
    #pragma unroll
    for (int i = 0; i < 4; ++i)
        #pragma unroll
        for (int j = 0; j < 6; ++j) acc[i][j] = 0ull;

    float4 va0, va1, vb0, vb1;
    va0 = *(const float4*)(g_A + (size_t)(bm + ar0) * DV + ac0 * 4);
    va1 = *(const float4*)(g_A + (size_t)(bm + ar1) * DV + ac1 * 4);
    vb0 = *(const float4*)(W + (size_t)br0 * DT + bn + bc0 * 4);
    if (bv1) vb1 = *(const float4*)(W + (size_t)br1 * DT + bn + bc1 * 4);
    {
        As[0][ac0 * 4 + 0][ar0] = va0.x; As[0][ac0 * 4 + 1][ar0] = va0.y;
        As[0][ac0 * 4 + 2][ar0] = va0.z; As[0][ac0 * 4 + 3][ar0] = va0.w;
        As[0][ac1 * 4 + 0][ar1] = va1.x; As[0][ac1 * 4 + 1][ar1] = va1.y;
        As[0][ac1 * 4 + 2][ar1] = va1.z; As[0][ac1 * 4 + 3][ar1] = va1.w;
        *(float4*)&Bs[0][br0][bc0 * 4] = vb0;
        if (bv1) *(float4*)&Bs[0][br1][bc1 * 4] = vb1;
    }
    __syncthreads();

    const int NT = DV / BK;  // 64
    int cur = 0;
    for (int t = 0; t < NT; ++t) {
        const int k0n = (t + 1) * BK;
        if (t + 1 < NT) {
            va0 = *(const float4*)(g_A + (size_t)(bm + ar0) * DV + k0n + ac0 * 4);
            va1 = *(const float4*)(g_A + (size_t)(bm + ar1) * DV + k0n + ac1 * 4);
            vb0 = *(const float4*)(W + (size_t)(k0n + br0) * DT + bn + bc0 * 4);
            if (bv1) vb1 = *(const float4*)(W + (size_t)(k0n + br1) * DT + bn + bc1 * 4);
        }

        #pragma unroll
        for (int k = 0; k < BK; ++k) {
            unsigned long long a0 = *(const unsigned long long*)&As[cur][k][ty * 8 + 0];
            unsigned long long a1 = *(const unsigned long long*)&As[cur][k][ty * 8 + 2];
            unsigned long long a2 = *(const unsigned long long*)&As[cur][k][ty * 8 + 4];
            unsigned long long a3 = *(const unsigned long long*)&As[cur][k][ty * 8 + 6];
            float2 q0 = *(const float2*)&Bs[cur][k][tx * 6 + 0];
            float2 q1 = *(const float2*)&Bs[cur][k][tx * 6 + 2];
            float2 q2 = *(const float2*)&Bs[cur][k][tx * 6 + 4];
            unsigned long long b0 = pack2(q0.x, q0.x);
            unsigned long long b1 = pack2(q0.y, q0.y);
            unsigned long long b2 = pack2(q1.x, q1.x);
            unsigned long long b3 = pack2(q1.y, q1.y);
            unsigned long long b4 = pack2(q2.x, q2.x);
            unsigned long long b5 = pack2(q2.y, q2.y);
            #pragma unroll
            for (int ii = 0; ii < 4; ++ii) {
                unsigned long long a = (ii == 0) ? a0 : (ii == 1) ? a1 : (ii == 2) ? a2 : a3;
                acc[ii][0] = fma2(a, b0, acc[ii][0]);
                acc[ii][1] = fma2(a, b1, acc[ii][1]);
                acc[ii][2] = fma2(a, b2, acc[ii][2]);
                acc[ii][3] = fma2(a, b3, acc[ii][3]);
                acc[ii][4] = fma2(a, b4, acc[ii][4]);
                acc[ii][5] = fma2(a, b5, acc[ii][5]);
            }
        }

        if (t + 1 < NT) {
            const int nxt = cur ^ 1;
            As[nxt][ac0 * 4 + 0][ar0] = va0.x; As[nxt][ac0 * 4 + 1][ar0] = va0.y;
            As[nxt][ac0 * 4 + 2][ar0] = va0.z; As[nxt][ac0 * 4 + 3][ar0] = va0.w;
            As[nxt][ac1 * 4 + 0][ar1] = va1.x; As[nxt][ac1 * 4 + 1][ar1] = va1.y;
            As[nxt][ac1 * 4 + 2][ar1] = va1.z; As[nxt][ac1 * 4 + 3][ar1] = va1.w;
            *(float4*)&Bs[nxt][br0][bc0 * 4] = vb0;
            if (bv1) *(float4*)&Bs[nxt][br1][bc1 * 4] = vb1;
        }
        __syncthreads();
        cur ^= 1;
    }

    // epilogue: bias add, C store, deterministic fused pooling
    float b6[6];
    {
        float2 u0 = *(const float2*)(bias + bn + tx * 6 + 0);
        float2 u1 = *(const float2*)(bias + bn + tx * 6 + 2);
        float2 u2 = *(const float2*)(bias + bn + tx * 6 + 4);
        b6[0] = u0.x; b6[1] = u0.y; b6[2] = u1.x;
        b6[3] = u1.y; b6[4] = u2.x; b6[5] = u2.y;
    }
    float cs[6] = {0.f, 0.f, 0.f, 0.f, 0.f, 0.f};
    #pragma unroll
    for (int ii = 0; ii < 4; ++ii) {
        float lo[6], hi[6];
        #pragma unroll
        for (int c = 0; c < 6; ++c) {
            unpack2(acc[ii][c], lo[c], hi[c]);
            lo[c] += b6[c]; hi[c] += b6[c];
            cs[c] += lo[c] + hi[c];
        }
        const int m0 = bm + ty * 8 + 2 * ii;
        float* p0 = g_C + (size_t)m0 * DT + bn + tx * 6;
        float* p1 = g_C + (size_t)(m0 + 1) * DT + bn + tx * 6;
        *(float2*)(p0 + 0) = make_float2(lo[0], lo[1]);
        *(float2*)(p0 + 2) = make_float2(lo[2], lo[3]);
        *(float2*)(p0 + 4) = make_float2(lo[4], lo[5]);
        *(float2*)(p1 + 0) = make_float2(hi[0], hi[1]);
        *(float2*)(p1 + 2) = make_float2(hi[2], hi[3]);
        *(float2*)(p1 + 4) = make_float2(hi[4], hi[5]);
    }
    #pragma unroll
    for (int c = 0; c < 6; ++c)
        s_part[ty][tx * 6 + c] = cs[c];
    __syncthreads();
    // fixed-order reduction: 4 batch slots x 96 cols = 384 sums of 4 partials
    for (int idx = tid; idx < 4 * BN; idx += 256) {
        const int bl = idx / BN, col = idx % BN;
        float s = s_part[bl * 4 + 0][col];
        s += s_part[bl * 4 + 1][col];
        s += s_part[bl * 4 + 2][col];
        s += s_part[bl * 4 + 3][col];
        g_pool[(size_t)(blockIdx.y * 4 + bl) * DT + bn + col] = s * (1.0f / NSEG);
    }
}

// ---------------------------------------------------------------------------
// K3: per-row sim + CE term. 64 blocks x 256 threads.
// Block i computes sim row i AND all diagonals (free on same rj loads).
// The lse is computed EXACTLY: diagonal (always the max, v_ii ~ 14.3 vs
// off-diag ~0.5) is separated, the 63 tiny exps are summed in DOUBLE and
// log1p'd in double. This removes the fp32 "1 + tiny" rounding lottery that
// caused rel_err to wander (8.4e-4 / 2.6e-3 / 1.14e-3 across orderings);
// residual error is now only the reference's own fp32 lse rounding.
// ---------------------------------------------------------------------------
__global__ void k_post(void) {
    const int i = blockIdx.x;
    const int tid = threadIdx.x;
    const int wid = tid >> 5, lane = tid & 31;
    __shared__ float s_sim[B_], s_diag[B_];
    __shared__ double s_red[2];

    const float4* Ri = (const float4*)(g_pool + (size_t)i * DT);
    float4 ri[6];
    #pragma unroll
    for (int c = 0; c < 6; ++c) ri[c] = Ri[lane + 32 * c];

    #pragma unroll
    for (int jj = 0; jj < 8; ++jj) {
        const int j = wid * 8 + jj;
        const float4* Rj = (const float4*)(g_pool + (size_t)j * DT);
        float sij = 0.f, sjj = 0.f;
        #pragma unroll
        for (int c = 0; c < 6; ++c) {
            float4 r = Rj[lane + 32 * c];
            sij = fmaf(ri[c].x, r.x, sij); sjj = fmaf(r.x, r.x, sjj);
            sij = fmaf(ri[c].y, r.y, sij); sjj = fmaf(r.y, r.y, sjj);
            sij = fmaf(ri[c].z, r.z, sij); sjj = fmaf(r.z, r.z, sjj);
            sij = fmaf(ri[c].w, r.w, sij); sjj = fmaf(r.w, r.w, sjj);
        }
        #pragma unroll
        for (int off = 16; off > 0; off >>= 1) {
            sij += __shfl_down_sync(0xffffffffu, sij, off);
            sjj += __shfl_down_sync(0xffffffffu, sjj, off);
        }
        if (lane == 0) { s_sim[j] = sij; s_diag[j] = sjj; }
    }
    __syncthreads();

    // exact lse in double: rowloss = log1p( sum_{j!=i} exp(v_ij - v_ii) )
    if (tid < B_) {
        const double dii  = (double)s_diag[i];
        const double invi = 1.0 / sqrt(dii);
        const double vii  = (double)s_sim[i] / dii * INV_TEMP;
        const double vj   = (double)s_sim[tid] * invi
                          / sqrt((double)s_diag[tid]) * INV_TEMP;
        double e = (tid == i) ? 0.0 : exp(vj - vii);
        #pragma unroll
        for (int off = 16; off > 0; off >>= 1)
            e += __shfl_down_sync(0xffffffffu, e, off);
        if (lane == 0) s_red[wid] = e;
    }
    __syncthreads();
    if (tid == 0)
        g_rowloss[i] = log1p(s_red[0] + s_red[1]);
}

// ---------------------------------------------------------------------------
// K-TEXT (side stream, independent of everything but ids/wte):
// ballot-scan ranks; copy wte rows for NON-placeholder tokens only.
// grid=512 (b*8+chunk), 512 threads. 8 threads per token x 24 float4.
// ---------------------------------------------------------------------------
__global__ void __launch_bounds__(512, 2)
k_emb_text(const float* __restrict__ wte,
           const int* __restrict__ ids,
           const int* __restrict__ ph_ptr,
           float* __restrict__ out) {
    const int b = blockIdx.x >> 3;
    const int c = blockIdx.x & 7;     // 64-token chunk within the row
    const int tid = threadIdx.x;      // 0..511

    __shared__ int s_ids[S_];
    __shared__ unsigned s_bal[16];
    __shared__ const float* s_src[64];

    const int ph = *ph_ptr;
    const int id = ids[b * S_ + tid];
    s_ids[tid] = id;
    const unsigned bal = __ballot_sync(0xffffffffu, id == ph);
    if ((tid & 31) == 0) s_bal[tid >> 5] = bal;
    __syncthreads();

    if (tid < 64) {
        const int s = c * 64 + tid;
        const int g = s >> 5, l = s & 31;
        int pre = 0;
        for (int gg = 0; gg < g; ++gg) pre += __popc(s_bal[gg]);
        const unsigned bg = s_bal[g];
        const int incl = pre + __popc(bg & (0xffffffffu >> (31 - l)));
        const bool isph = (s_ids[s] == ph);
        const int r = incl - 1;
        // placeholder-valid tokens are handled by k_emb_ph
        s_src[tid] = (isph && r < NSEG) ? (const float*)0
                                        : (wte + (size_t)s_ids[s] * DT);
    }
    __syncthreads();

    const int u = tid >> 3, sub = tid & 7;   // 8 threads per token
    const float4* src = (const float4*)s_src[u];
    if (src) {
        float4* dst = (float4*)(out + ((size_t)(b * S_ + c * 64 + u)) * DT);
        #pragma unroll
        for (int rr = 0; rr < 24; ++rr)
            dst[sub + 8 * rr] = src[sub + 8 * rr];
    }
}

// ---------------------------------------------------------------------------
// K-PH (after gemm+post): each block re-scans its batch row, copies the 32
// seg_means rows into the placeholder positions, block 0 reduces rowloss
// in double. grid=64, 512 threads. 16 threads per row x 12 float4.
// ---------------------------------------------------------------------------
__global__ void __launch_bounds__(512, 2)
k_emb_ph(const int* __restrict__ ids,
         const int* __restrict__ ph_ptr,
         float* __restrict__ out,
         float* __restrict__ loss_out) {
    const int b = blockIdx.x;
    const int tid = threadIdx.x;      // 0..511

    __shared__ unsigned s_bal[16];
    __shared__ int s_pos[NSEG];

    if (tid < NSEG) s_pos[tid] = -1;
    const int ph = *ph_ptr;
    const int id = ids[b * S_ + tid];
    const bool isph = (id == ph);
    const unsigned bal = __ballot_sync(0xffffffffu, isph);
    if ((tid & 31) == 0) s_bal[tid >> 5] = bal;
    __syncthreads();

    {
        const int g = tid >> 5, l = tid & 31;
        int pre = 0;
        for (int gg = 0; gg < g; ++gg) pre += __popc(s_bal[gg]);
        const int incl = pre + __popc(s_bal[g] & (0xffffffffu >> (31 - l)));
        const int r = incl - 1;
        if (isph && r < NSEG) s_pos[r] = tid;
    }
    __syncthreads();

    const int row = tid >> 4, sub = tid & 15;   // 32 rows x 16 threads
    const int pos = s_pos[row];
    if (pos >= 0) {
        const float4* src = (const float4*)(g_C + (size_t)(b * NSEG + row) * DT);
        float4* dst = (float4*)(out + ((size_t)(b * S_ + pos)) * DT);
        #pragma unroll
        for (int rr = 0; rr < 12; ++rr)
            dst[sub + 16 * rr] = src[sub + 16 * rr];
    }

    if (b == 0 && tid == 0) {
        double t = 0.0;
        #pragma unroll
        for (int j = 0; j < B_; ++j) t += g_rowloss[j];
        *loss_out = (float)(t * (1.0 / B_));
    }
}

// ---------------------------------------------------------------------------
// Fork-join launch: the wte gather/copy (94% of embedding traffic) depends
// only on ids/wte, so it runs on a side stream concurrent with the
// compute-bound ln->gemm->post chain; the placeholder rows join after.
// Static stream/events: created once (host-side only, no device memory);
// captured ops are identical on every call.
// ---------------------------------------------------------------------------
struct HxStreams {
    cudaStream_t s2;
    cudaEvent_t  fork, join;
    HxStreams() {
        cudaStreamCreateWithFlags(&s2, cudaStreamNonBlocking);
        cudaEventCreateWithFlags(&fork, cudaEventDisableTiming);
        cudaEventCreateWithFlags(&join, cudaEventDisableTiming);
    }
};

extern "C" void kernel_launch(void* const* d_in, const int* in_sizes, int n_in,
                              void* d_out, int out_size) {
    static HxStreams hx;   // one-time host-side setup; identical work per call

    const float* vis   = (const float*)d_in[0];  // [64,256,1024]
    const float* gamma = (const float*)d_in[1];  // [1024]
    const float* beta  = (const float*)d_in[2];  // [1024]
    const float* Wp    = (const float*)d_in[3];  // [1024,768]
    const float* bp    = (const float*)d_in[4];  // [768]
    const float* wte   = (const float*)d_in[5];  // [50257,768]
    const int*   ids   = (const int*)d_in[6];    // [64,512]
    const int*   ph    = (const int*)d_in[7];    // scalar

    float* out = (float*)d_out;
    float* loss_out = out + (out_size - 1);

    // fork: side stream does the wte text-embedding copy
    cudaEventRecord(hx.fork, 0);
    cudaStreamWaitEvent(hx.s2, hx.fork, 0);
    k_emb_text<<<B_ * 8, 512, 0, hx.s2>>>(wte, ids, ph, out);
    cudaEventRecord(hx.join, hx.s2);

    // main chain
    k_ln_seg<<<M_, 256>>>(vis, gamma, beta);
    {
        dim3 grid(DT / BN, M_ / BM);
        k_gemm<<<grid, 256>>>(Wp, bp);
    }
    k_post<<<B_, 256>>>();

    // join, then placeholder rows + loss
    cudaStreamWaitEvent(0, hx.join, 0);
    k_emb_ph<<<B_, 512>>>(ids, ph, out, loss_out);
}

// round 14
// speedup vs baseline: 1.3393x; 1.0013x over previous
#include <cuda_runtime.h>
#include <cuda_bf16.h>
#include <math.h>

// Problem constants (fixed by setup_inputs)
#define B_   64
#define P_   256
#define DV   1024
#define DT   768
#define S_   512
#define NSEG 32
#define PPT  8
#define M_   (B_ * NSEG)   // 2048 GEMM rows
#define EPSV 1e-5f
#define INV_TEMP (1.0 / 0.07)

// Scratch (device globals; no allocations allowed)
__device__ float  g_A[M_ * DV];       // seg-averaged normalized features  [2048,1024]
__device__ float  g_C[M_ * DT];       // seg_means = A @ W + b             [2048,768]
__device__ float  g_pool[B_ * DT];    // pooled (mean over segs)           [64,768]
__device__ double g_rowloss[B_];      // per-row CE terms (double)

// ---- packed f32x2 helpers (Blackwell FFMA2 path) --------------------------
__device__ __forceinline__ unsigned long long pack2(float x, float y) {
    unsigned long long r;
    asm("mov.b64 %0, {%1, %2};" : "=l"(r) : "f"(x), "f"(y));
    return r;
}
__device__ __forceinline__ void unpack2(unsigned long long v, float& x, float& y) {
    asm("mov.b64 {%0, %1}, %2;" : "=f"(x), "=f"(y) : "l"(v));
}
__device__ __forceinline__ unsigned long long fma2(unsigned long long a,
                                                   unsigned long long b,
                                                   unsigned long long c) {
    unsigned long long d;
    asm("fma.rn.f32x2 %0, %1, %2, %3;" : "=l"(d) : "l"(a), "l"(b), "l"(c));
    return d;
}

// ---------------------------------------------------------------------------
// K1: per-(b,seg) block. Preload all 8 patch rows (MLP=8), LayerNorm each,
// accumulate; write A = gamma * (sum xhat / 8) + beta.  grid=2048, 256 thr.
// ---------------------------------------------------------------------------
__global__ void k_ln_seg(const float* __restrict__ x,
                         const float* __restrict__ gamma,
                         const float* __restrict__ beta) {
    const int blk = blockIdx.x;            // b*32 + seg
    const int b = blk >> 5, seg = blk & 31;
    const int t = threadIdx.x;             // 0..255, one float4 per row
    const int wid = t >> 5, lane = t & 31;

    __shared__ float s_s[8][8], s_q[8][8];
    __shared__ float2 s_mi[8];

    const float* base = x + ((size_t)(b * P_ + seg * PPT)) * DV;

    float4 v[8];
    #pragma unroll
    for (int pp = 0; pp < PPT; ++pp)
        v[pp] = ((const float4*)(base + (size_t)pp * DV))[t];

    #pragma unroll
    for (int pp = 0; pp < PPT; ++pp) {
        float s  = v[pp].x + v[pp].y + v[pp].z + v[pp].w;
        float sq = v[pp].x * v[pp].x + v[pp].y * v[pp].y
                 + v[pp].z * v[pp].z + v[pp].w * v[pp].w;
        #pragma unroll
        for (int off = 16; off > 0; off >>= 1) {
            s  += __shfl_down_sync(0xffffffffu, s,  off);
            sq += __shfl_down_sync(0xffffffffu, sq, off);
        }
        if (lane == 0) { s_s[pp][wid] = s; s_q[pp][wid] = sq; }
    }
    __syncthreads();

    if (lane < 8) {
        float s = s_s[wid][lane];
        float q = s_q[wid][lane];
        #pragma unroll
        for (int off = 4; off > 0; off >>= 1) {
            s += __shfl_down_sync(0x000000ffu, s, off);
            q += __shfl_down_sync(0x000000ffu, q, off);
        }
        if (lane == 0) {
            float mean = s * (1.0f / DV);
            float var  = q * (1.0f / DV) - mean * mean;
            s_mi[wid] = make_float2(mean, rsqrtf(var + EPSV));
        }
    }
    __syncthreads();

    float4 acc = make_float4(0.f, 0.f, 0.f, 0.f);
    #pragma unroll
    for (int pp = 0; pp < PPT; ++pp) {
        const float2 mi = s_mi[pp];
        acc.x += (v[pp].x - mi.x) * mi.y;
        acc.y += (v[pp].y - mi.x) * mi.y;
        acc.z += (v[pp].z - mi.x) * mi.y;
        acc.w += (v[pp].w - mi.x) * mi.y;
    }

    const float4 g  = ((const float4*)gamma)[t];
    const float4 bb = ((const float4*)beta)[t];
    float4 o;
    o.x = g.x * acc.x * 0.125f + bb.x;
    o.y = g.y * acc.y * 0.125f + bb.y;
    o.z = g.z * acc.z * 0.125f + bb.z;
    o.w = g.w * acc.w * 0.125f + bb.w;
    ((float4*)(g_A + (size_t)blk * DV))[t] = o;
}

// ---------------------------------------------------------------------------
// K2: GEMM  C[2048,768] = A[2048,1024] @ W[1024,768] + bias, fused pooling.
// BM=128 (= 4 batches x 32 segs), BN=96, BK=16, 256 threads, FFMA2 accums,
// double-buffered smem. grid = (8,16) = 128 blocks -> one wave.
// Deterministic pooling epilogue (fixed-order partials, no atomics).
// ---------------------------------------------------------------------------
#define BM 128
#define BN 96
#define BK 16
__global__ void __launch_bounds__(256, 1)
k_gemm(const float* __restrict__ W, const float* __restrict__ bias) {
    __shared__ __align__(16) float As[2][BK][BM];
    __shared__ __align__(16) float Bs[2][BK][BN];
    __shared__ float s_part[16][BN];   // per-ty column partials

    const int bm = blockIdx.y * BM;
    const int bn = blockIdx.x * BN;
    const int tid = threadIdx.x;          // 256
    const int tx = tid & 15;              // col group: 6 cols each
    const int ty = tid >> 4;              // row group: 8 rows each (4 pairs)

    const int ar0 = tid >> 2,          ac0 = tid & 3;
    const int ar1 = (tid + 256) >> 2,  ac1 = (tid + 256) & 3;
    const int br0 = tid / 24,  bc0 = tid % 24;
    const int br1 = (tid + 256) / 24, bc1 = (tid + 256) % 24;
    const bool bv1 = (tid + 256) < 384;

    unsigned long long acc[4][6];
    #pragma unroll
    for (int i = 0; i < 4; ++i)
        #pragma unroll
        for (int j = 0; j < 6; ++j) acc[i][j] = 0ull;

    float4 va0, va1, vb0, vb1;
    va0 = *(const float4*)(g_A + (size_t)(bm + ar0) * DV + ac0 * 4);
    va1 = *(const float4*)(g_A + (size_t)(bm + ar1) * DV + ac1 * 4);
    vb0 = *(const float4*)(W + (size_t)br0 * DT + bn + bc0 * 4);
    if (bv1) vb1 = *(const float4*)(W + (size_t)br1 * DT + bn + bc1 * 4);
    {
        As[0][ac0 * 4 + 0][ar0] = va0.x; As[0][ac0 * 4 + 1][ar0] = va0.y;
        As[0][ac0 * 4 + 2][ar0] = va0.z; As[0][ac0 * 4 + 3][ar0] = va0.w;
        As[0][ac1 * 4 + 0][ar1] = va1.x; As[0][ac1 * 4 + 1][ar1] = va1.y;
        As[0][ac1 * 4 + 2][ar1] = va1.z; As[0][ac1 * 4 + 3][ar1] = va1.w;
        *(float4*)&Bs[0][br0][bc0 * 4] = vb0;
        if (bv1) *(float4*)&Bs[0][br1][bc1 * 4] = vb1;
    }
    __syncthreads();

    const int NT = DV / BK;  // 64
    int cur = 0;
    for (int t = 0; t < NT; ++t) {
        const int k0n = (t + 1) * BK;
        if (t + 1 < NT) {
            va0 = *(const float4*)(g_A + (size_t)(bm + ar0) * DV + k0n + ac0 * 4);
            va1 = *(const float4*)(g_A + (size_t)(bm + ar1) * DV + k0n + ac1 * 4);
            vb0 = *(const float4*)(W + (size_t)(k0n + br0) * DT + bn + bc0 * 4);
            if (bv1) vb1 = *(const float4*)(W + (size_t)(k0n + br1) * DT + bn + bc1 * 4);
        }

        #pragma unroll
        for (int k = 0; k < BK; ++k) {
            unsigned long long a0 = *(const unsigned long long*)&As[cur][k][ty * 8 + 0];
            unsigned long long a1 = *(const unsigned long long*)&As[cur][k][ty * 8 + 2];
            unsigned long long a2 = *(const unsigned long long*)&As[cur][k][ty * 8 + 4];
            unsigned long long a3 = *(const unsigned long long*)&As[cur][k][ty * 8 + 6];
            float2 q0 = *(const float2*)&Bs[cur][k][tx * 6 + 0];
            float2 q1 = *(const float2*)&Bs[cur][k][tx * 6 + 2];
            float2 q2 = *(const float2*)&Bs[cur][k][tx * 6 + 4];
            unsigned long long b0 = pack2(q0.x, q0.x);
            unsigned long long b1 = pack2(q0.y, q0.y);
            unsigned long long b2 = pack2(q1.x, q1.x);
            unsigned long long b3 = pack2(q1.y, q1.y);
            unsigned long long b4 = pack2(q2.x, q2.x);
            unsigned long long b5 = pack2(q2.y, q2.y);
            #pragma unroll
            for (int ii = 0; ii < 4; ++ii) {
                unsigned long long a = (ii == 0) ? a0 : (ii == 1) ? a1 : (ii == 2) ? a2 : a3;
                acc[ii][0] = fma2(a, b0, acc[ii][0]);
                acc[ii][1] = fma2(a, b1, acc[ii][1]);
                acc[ii][2] = fma2(a, b2, acc[ii][2]);
                acc[ii][3] = fma2(a, b3, acc[ii][3]);
                acc[ii][4] = fma2(a, b4, acc[ii][4]);
                acc[ii][5] = fma2(a, b5, acc[ii][5]);
            }
        }

        if (t + 1 < NT) {
            const int nxt = cur ^ 1;
            As[nxt][ac0 * 4 + 0][ar0] = va0.x; As[nxt][ac0 * 4 + 1][ar0] = va0.y;
            As[nxt][ac0 * 4 + 2][ar0] = va0.z; As[nxt][ac0 * 4 + 3][ar0] = va0.w;
            As[nxt][ac1 * 4 + 0][ar1] = va1.x; As[nxt][ac1 * 4 + 1][ar1] = va1.y;
            As[nxt][ac1 * 4 + 2][ar1] = va1.z; As[nxt][ac1 * 4 + 3][ar1] = va1.w;
            *(float4*)&Bs[nxt][br0][bc0 * 4] = vb0;
            if (bv1) *(float4*)&Bs[nxt][br1][bc1 * 4] = vb1;
        }
        __syncthreads();
        cur ^= 1;
    }

    // epilogue: bias add, C store, deterministic fused pooling
    float b6[6];
    {
        float2 u0 = *(const float2*)(bias + bn + tx * 6 + 0);
        float2 u1 = *(const float2*)(bias + bn + tx * 6 + 2);
        float2 u2 = *(const float2*)(bias + bn + tx * 6 + 4);
        b6[0] = u0.x; b6[1] = u0.y; b6[2] = u1.x;
        b6[3] = u1.y; b6[4] = u2.x; b6[5] = u2.y;
    }
    float cs[6] = {0.f, 0.f, 0.f, 0.f, 0.f, 0.f};
    #pragma unroll
    for (int ii = 0; ii < 4; ++ii) {
        float lo[6], hi[6];
        #pragma unroll
        for (int c = 0; c < 6; ++c) {
            unpack2(acc[ii][c], lo[c], hi[c]);
            lo[c] += b6[c]; hi[c] += b6[c];
            cs[c] += lo[c] + hi[c];
        }
        const int m0 = bm + ty * 8 + 2 * ii;
        float* p0 = g_C + (size_t)m0 * DT + bn + tx * 6;
        float* p1 = g_C + (size_t)(m0 + 1) * DT + bn + tx * 6;
        *(float2*)(p0 + 0) = make_float2(lo[0], lo[1]);
        *(float2*)(p0 + 2) = make_float2(lo[2], lo[3]);
        *(float2*)(p0 + 4) = make_float2(lo[4], lo[5]);
        *(float2*)(p1 + 0) = make_float2(hi[0], hi[1]);
        *(float2*)(p1 + 2) = make_float2(hi[2], hi[3]);
        *(float2*)(p1 + 4) = make_float2(hi[4], hi[5]);
    }
    #pragma unroll
    for (int c = 0; c < 6; ++c)
        s_part[ty][tx * 6 + c] = cs[c];
    __syncthreads();
    // fixed-order reduction: 4 batch slots x 96 cols = 384 sums of 4 partials
    for (int idx = tid; idx < 4 * BN; idx += 256) {
        const int bl = idx / BN, col = idx % BN;
        float s = s_part[bl * 4 + 0][col];
        s += s_part[bl * 4 + 1][col];
        s += s_part[bl * 4 + 2][col];
        s += s_part[bl * 4 + 3][col];
        g_pool[(size_t)(blockIdx.y * 4 + bl) * DT + bn + col] = s * (1.0f / NSEG);
    }
}

// ---------------------------------------------------------------------------
// K3: per-row sim + CE term. 64 blocks x 512 threads (16 warps, 4 j's each:
// doubled parallelism vs round 13 to cut the L2-latency critical path).
// Exact lse: diagonal separated, 63 tiny exps summed in double, log1p.
// ---------------------------------------------------------------------------
__global__ void __launch_bounds__(512, 2)
k_post(void) {
    const int i = blockIdx.x;
    const int tid = threadIdx.x;
    const int wid = tid >> 5, lane = tid & 31;
    __shared__ float s_sim[B_], s_diag[B_];
    __shared__ double s_red[2];

    const float4* Ri = (const float4*)(g_pool + (size_t)i * DT);
    float4 ri[6];
    #pragma unroll
    for (int c = 0; c < 6; ++c) ri[c] = Ri[lane + 32 * c];

    #pragma unroll
    for (int jj = 0; jj < 4; ++jj) {
        const int j = wid * 4 + jj;
        const float4* Rj = (const float4*)(g_pool + (size_t)j * DT);
        float sij = 0.f, sjj = 0.f;
        #pragma unroll
        for (int c = 0; c < 6; ++c) {
            float4 r = Rj[lane + 32 * c];
            sij = fmaf(ri[c].x, r.x, sij); sjj = fmaf(r.x, r.x, sjj);
            sij = fmaf(ri[c].y, r.y, sij); sjj = fmaf(r.y, r.y, sjj);
            sij = fmaf(ri[c].z, r.z, sij); sjj = fmaf(r.z, r.z, sjj);
            sij = fmaf(ri[c].w, r.w, sij); sjj = fmaf(r.w, r.w, sjj);
        }
        #pragma unroll
        for (int off = 16; off > 0; off >>= 1) {
            sij += __shfl_down_sync(0xffffffffu, sij, off);
            sjj += __shfl_down_sync(0xffffffffu, sjj, off);
        }
        if (lane == 0) { s_sim[j] = sij; s_diag[j] = sjj; }
    }
    __syncthreads();

    // exact lse in double: rowloss = log1p( sum_{j!=i} exp(v_ij - v_ii) )
    if (tid < B_) {
        const double dii  = (double)s_diag[i];
        const double invi = 1.0 / sqrt(dii);
        const double vii  = (double)s_sim[i] / dii * INV_TEMP;
        const double vj   = (double)s_sim[tid] * invi
                          / sqrt((double)s_diag[tid]) * INV_TEMP;
        double e = (tid == i) ? 0.0 : exp(vj - vii);
        #pragma unroll
        for (int off = 16; off > 0; off >>= 1)
            e += __shfl_down_sync(0xffffffffu, e, off);
        if (lane == 0) s_red[wid] = e;
    }
    __syncthreads();
    if (tid == 0)
        g_rowloss[i] = log1p(s_red[0] + s_red[1]);
}

// ---------------------------------------------------------------------------
// K-TEXT (side stream): ballot-scan ranks; copy wte rows for NON-placeholder
// tokens. grid=512 (b*8+chunk), 256 threads, launch_bounds(256,3) so blocks
// CO-RESIDE with ln/gemm (round-13's 512thr x 63reg variant filled the whole
// register file at 2 blocks/SM and forced serial execution).
// 4 threads per token x 48 float4.
// ---------------------------------------------------------------------------
__global__ void __launch_bounds__(256, 3)
k_emb_text(const float* __restrict__ wte,
           const int* __restrict__ ids,
           const int* __restrict__ ph_ptr,
           float* __restrict__ out) {
    const int b = blockIdx.x >> 3;
    const int c = blockIdx.x & 7;     // 64-token chunk within the row
    const int tid = threadIdx.x;      // 0..255

    __shared__ int s_ids[S_];
    __shared__ unsigned s_bal[16];
    __shared__ const float* s_src[64];

    const int ph = *ph_ptr;
    const int id0 = ids[b * S_ + tid];
    const int id1 = ids[b * S_ + 256 + tid];
    s_ids[tid] = id0;
    s_ids[256 + tid] = id1;
    const unsigned bal0 = __ballot_sync(0xffffffffu, id0 == ph);
    const unsigned bal1 = __ballot_sync(0xffffffffu, id1 == ph);
    if ((tid & 31) == 0) {
        s_bal[tid >> 5] = bal0;
        s_bal[8 + (tid >> 5)] = bal1;
    }
    __syncthreads();

    if (tid < 64) {
        const int s = c * 64 + tid;
        const int g = s >> 5, l = s & 31;
        int pre = 0;
        for (int gg = 0; gg < g; ++gg) pre += __popc(s_bal[gg]);
        const unsigned bg = s_bal[g];
        const int incl = pre + __popc(bg & (0xffffffffu >> (31 - l)));
        const bool isph = (s_ids[s] == ph);
        const int r = incl - 1;
        // placeholder-valid tokens are handled by k_emb_ph
        s_src[tid] = (isph && r < NSEG) ? (const float*)0
                                        : (wte + (size_t)s_ids[s] * DT);
    }
    __syncthreads();

    const int u = tid >> 2, sub = tid & 3;   // 4 threads per token
    const float4* src = (const float4*)s_src[u];
    if (src) {
        float4* dst = (float4*)(out + ((size_t)(b * S_ + c * 64 + u)) * DT);
        #pragma unroll 8
        for (int rr = 0; rr < 48; ++rr)
            dst[sub + 4 * rr] = src[sub + 4 * rr];
    }
}

// ---------------------------------------------------------------------------
// K-PH (after gemm+post): each block re-scans its batch row, copies the 32
// seg_means rows into the placeholder positions, block 0 reduces rowloss
// in double. grid=64, 512 threads. 16 threads per row x 12 float4.
// ---------------------------------------------------------------------------
__global__ void __launch_bounds__(512, 2)
k_emb_ph(const int* __restrict__ ids,
         const int* __restrict__ ph_ptr,
         float* __restrict__ out,
         float* __restrict__ loss_out) {
    const int b = blockIdx.x;
    const int tid = threadIdx.x;      // 0..511

    __shared__ unsigned s_bal[16];
    __shared__ int s_pos[NSEG];

    if (tid < NSEG) s_pos[tid] = -1;
    const int ph = *ph_ptr;
    const int id = ids[b * S_ + tid];
    const bool isph = (id == ph);
    const unsigned bal = __ballot_sync(0xffffffffu, isph);
    if ((tid & 31) == 0) s_bal[tid >> 5] = bal;
    __syncthreads();

    {
        const int g = tid >> 5, l = tid & 31;
        int pre = 0;
        for (int gg = 0; gg < g; ++gg) pre += __popc(s_bal[gg]);
        const int incl = pre + __popc(s_bal[g] & (0xffffffffu >> (31 - l)));
        const int r = incl - 1;
        if (isph && r < NSEG) s_pos[r] = tid;
    }
    __syncthreads();

    const int row = tid >> 4, sub = tid & 15;   // 32 rows x 16 threads
    const int pos = s_pos[row];
    if (pos >= 0) {
        const float4* src = (const float4*)(g_C + (size_t)(b * NSEG + row) * DT);
        float4* dst = (float4*)(out + ((size_t)(b * S_ + pos)) * DT);
        #pragma unroll
        for (int rr = 0; rr < 12; ++rr)
            dst[sub + 16 * rr] = src[sub + 16 * rr];
    }

    if (b == 0 && tid == 0) {
        double t = 0.0;
        #pragma unroll
        for (int j = 0; j < B_; ++j) t += g_rowloss[j];
        *loss_out = (float)(t * (1.0 / B_));
    }
}

// ---------------------------------------------------------------------------
// Fork-join launch: wte gather/copy on a side stream, concurrent with the
// compute-bound ln->gemm->post chain. ln enqueued FIRST so its blocks get
// dispatch priority; emb_text blocks now co-reside (small RF footprint).
// ---------------------------------------------------------------------------
struct HxStreams {
    cudaStream_t s2;
    cudaEvent_t  fork, join;
    HxStreams() {
        cudaStreamCreateWithFlags(&s2, cudaStreamNonBlocking);
        cudaEventCreateWithFlags(&fork, cudaEventDisableTiming);
        cudaEventCreateWithFlags(&join, cudaEventDisableTiming);
    }
};

extern "C" void kernel_launch(void* const* d_in, const int* in_sizes, int n_in,
                              void* d_out, int out_size) {
    static HxStreams hx;   // one-time host-side setup; identical work per call

    const float* vis   = (const float*)d_in[0];  // [64,256,1024]
    const float* gamma = (const float*)d_in[1];  // [1024]
    const float* beta  = (const float*)d_in[2];  // [1024]
    const float* Wp    = (const float*)d_in[3];  // [1024,768]
    const float* bp    = (const float*)d_in[4];  // [768]
    const float* wte   = (const float*)d_in[5];  // [50257,768]
    const int*   ids   = (const int*)d_in[6];    // [64,512]
    const int*   ph    = (const int*)d_in[7];    // scalar

    float* out = (float*)d_out;
    float* loss_out = out + (out_size - 1);

    cudaEventRecord(hx.fork, 0);
    cudaStreamWaitEvent(hx.s2, hx.fork, 0);

    // main chain head first (dispatch priority for ln blocks)
    k_ln_seg<<<M_, 256>>>(vis, gamma, beta);

    // side stream: the big wte text-embedding copy (overlaps ln+gemm)
    k_emb_text<<<B_ * 8, 256, 0, hx.s2>>>(wte, ids, ph, out);
    cudaEventRecord(hx.join, hx.s2);

    // main chain
    {
        dim3 grid(DT / BN, M_ / BM);
        k_gemm<<<grid, 256>>>(Wp, bp);
    }
    k_post<<<B_, 512>>>();

    // join, then placeholder rows + loss
    cudaStreamWaitEvent(0, hx.join, 0);
    k_emb_ph<<<B_, 512>>>(ids, ph, out, loss_out);
}